// round 2
// baseline (speedup 1.0000x reference)
#include <cuda_runtime.h>
#include <mma.h>
using namespace nvcuda;

#define S_    2048
#define B_    2
#define D_    1024
#define H_    16
#define DH_   64
#define BH_   32          // B_*H_
#define ROWS_ 4096        // S_*B_
#define QLD_  3072        // row stride of g_qkv
#define ARS_  6144        // seq-row stride inside g_qkv = B_*QLD_

// ---- scratch (static device globals; no allocation) ----
__device__ float g_qkv[ROWS_ * 3072];                 // [s*B+b][3*H*DH]  (q|k|v)
__device__ float g_r  [S_ * D_];                      // [t][h*64+d]
__device__ float g_bd [(size_t)BH_ * S_ * S_];        // raw (q+v)·r  per (b,h)
__device__ float g_sc [(size_t)BH_ * S_ * S_];        // scores -> probs (in place)
__device__ float g_att[ROWS_ * D_];                   // attn_vec
__device__ float g_y  [ROWS_ * D_];                   // x + attn_out

using frA  = wmma::fragment<wmma::matrix_a, 16, 16, 8, wmma::precision::tf32, wmma::row_major>;
using frBr = wmma::fragment<wmma::matrix_b, 16, 16, 8, wmma::precision::tf32, wmma::row_major>;
using frBc = wmma::fragment<wmma::matrix_b, 16, 16, 8, wmma::precision::tf32, wmma::col_major>;
using frC  = wmma::fragment<wmma::accumulator, 16, 16, 8, float>;

__device__ __forceinline__ float t32(float x) { return wmma::__float_to_tf32(x); }

// ============================================================
// Generic 128x128 NN tf32 GEMM. MODE 0: g_qkv, 1: g_r,
// 2: g_y = g_att @ Wo + Xres (acc initialized from residual).
// ============================================================
template <int MODE>
__global__ __launch_bounds__(256) void wgemm_nn(const float* __restrict__ A,
                                                const float* __restrict__ Bw,
                                                const float* __restrict__ Xres,
                                                int M, int N, int K)
{
    __shared__ float As[128 * 36];   // A tile [128][32], ld 36
    __shared__ float Bs[32 * 132];   // B tile [32][128], ld 132
    const float* Ap = (MODE == 2) ? g_att : A;
    float* C = (MODE == 0) ? g_qkv : (MODE == 1) ? g_r : g_y;

    int tid = threadIdx.x;
    int w = tid >> 5, wm = w >> 1, wn = w & 1;
    size_t m0 = (size_t)blockIdx.y * 128;
    size_t n0 = (size_t)blockIdx.x * 128;

    frC acc[2][4];
#pragma unroll
    for (int mi = 0; mi < 2; mi++)
#pragma unroll
        for (int ni = 0; ni < 4; ni++) {
            if (MODE == 2)
                wmma::load_matrix_sync(acc[mi][ni],
                    Xres + (m0 + wm * 32 + mi * 16) * N + n0 + wn * 64 + ni * 16,
                    N, wmma::mem_row_major);
            else
                wmma::fill_fragment(acc[mi][ni], 0.f);
        }

    for (int kk = 0; kk < K; kk += 32) {
#pragma unroll
        for (int l = 0; l < 4; l++) {
            int idx = tid + l * 256;
            int r = idx >> 3, c4 = (idx & 7) << 2;
            float4 v = *(const float4*)(Ap + (m0 + r) * K + kk + c4);
            As[r * 36 + c4 + 0] = t32(v.x); As[r * 36 + c4 + 1] = t32(v.y);
            As[r * 36 + c4 + 2] = t32(v.z); As[r * 36 + c4 + 3] = t32(v.w);
        }
#pragma unroll
        for (int l = 0; l < 4; l++) {
            int idx = tid + l * 256;
            int r = idx >> 5, c4 = (idx & 31) << 2;
            float4 v = *(const float4*)(Bw + (size_t)(kk + r) * N + n0 + c4);
            Bs[r * 132 + c4 + 0] = t32(v.x); Bs[r * 132 + c4 + 1] = t32(v.y);
            Bs[r * 132 + c4 + 2] = t32(v.z); Bs[r * 132 + c4 + 3] = t32(v.w);
        }
        __syncthreads();
#pragma unroll
        for (int k8 = 0; k8 < 4; k8++) {
            frA a[2];
#pragma unroll
            for (int mi = 0; mi < 2; mi++)
                wmma::load_matrix_sync(a[mi], &As[(wm * 32 + mi * 16) * 36 + k8 * 8], 36);
#pragma unroll
            for (int ni = 0; ni < 4; ni++) {
                frBr bf;
                wmma::load_matrix_sync(bf, &Bs[(k8 * 8) * 132 + wn * 64 + ni * 16], 132);
#pragma unroll
                for (int mi = 0; mi < 2; mi++)
                    wmma::mma_sync(acc[mi][ni], a[mi], bf, acc[mi][ni]);
            }
        }
        __syncthreads();
    }
#pragma unroll
    for (int mi = 0; mi < 2; mi++)
#pragma unroll
        for (int ni = 0; ni < 4; ni++)
            wmma::store_matrix_sync(
                C + (m0 + wm * 32 + mi * 16) * N + n0 + wn * 64 + ni * 16,
                acc[mi][ni], N, wmma::mem_row_major);
}

// ============================================================
// Batched per-(b,h) NT tf32 GEMM over K=64, tile 128x128.
// MODE 0: Draw = (q + pos_bias_v) @ r^T        -> g_bd
// MODE 1: AC = (q + pos_bias_u) @ k^T, then add rel-shifted
//         Draw, scale 0.125, write             -> g_sc
// ============================================================
template <int MODE>
__global__ __launch_bounds__(256) void wscore(const float* __restrict__ bias_all)
{
    __shared__ float sbuf[9216];     // As: [0,4608)  Bs: [4608,9216)  (ld 36)
    float* As = sbuf;
    float* Bs = sbuf + 4608;
    int bh = blockIdx.z, b = bh >> 4, h = bh & 15;
    const float* Aq = g_qkv + b * QLD_ + h * 64;
    const float* Bp = (MODE == 0) ? (g_r + h * 64)
                                  : (g_qkv + b * QLD_ + 1024 + h * 64);
    size_t brs = (MODE == 0) ? (size_t)D_ : (size_t)ARS_;
    const float* bias = bias_all + h * 64;

    int tid = threadIdx.x;
    int w = tid >> 5, wm = w >> 1, wn = w & 1;
    int i0 = blockIdx.y * 128;
    int j0 = blockIdx.x * 128;

    frC acc[2][4];
#pragma unroll
    for (int mi = 0; mi < 2; mi++)
#pragma unroll
        for (int ni = 0; ni < 4; ni++) wmma::fill_fragment(acc[mi][ni], 0.f);

    for (int kk = 0; kk < 64; kk += 32) {
#pragma unroll
        for (int l = 0; l < 4; l++) {
            int idx = tid + l * 256;
            int r = idx >> 3, c4 = (idx & 7) << 2;
            float4 a4 = *(const float4*)(Aq + (size_t)(i0 + r) * ARS_ + kk + c4);
            float4 u4 = *(const float4*)(bias + kk + c4);
            As[r * 36 + c4 + 0] = t32(a4.x + u4.x);
            As[r * 36 + c4 + 1] = t32(a4.y + u4.y);
            As[r * 36 + c4 + 2] = t32(a4.z + u4.z);
            As[r * 36 + c4 + 3] = t32(a4.w + u4.w);
            float4 b4 = *(const float4*)(Bp + (size_t)(j0 + r) * brs + kk + c4);
            Bs[r * 36 + c4 + 0] = t32(b4.x); Bs[r * 36 + c4 + 1] = t32(b4.y);
            Bs[r * 36 + c4 + 2] = t32(b4.z); Bs[r * 36 + c4 + 3] = t32(b4.w);
        }
        __syncthreads();
#pragma unroll
        for (int k8 = 0; k8 < 4; k8++) {
            frA a[2];
#pragma unroll
            for (int mi = 0; mi < 2; mi++)
                wmma::load_matrix_sync(a[mi], &As[(wm * 32 + mi * 16) * 36 + k8 * 8], 36);
#pragma unroll
            for (int ni = 0; ni < 4; ni++) {
                frBc bf;
                wmma::load_matrix_sync(bf, &Bs[(wn * 64 + ni * 16) * 36 + k8 * 8], 36);
#pragma unroll
                for (int mi = 0; mi < 2; mi++)
                    wmma::mma_sync(acc[mi][ni], a[mi], bf, acc[mi][ni]);
            }
        }
        __syncthreads();
    }

    size_t base = (size_t)bh * S_ * S_;
    if (MODE == 0) {
#pragma unroll
        for (int mi = 0; mi < 2; mi++)
#pragma unroll
            for (int ni = 0; ni < 4; ni++)
                wmma::store_matrix_sync(
                    g_bd + base + (size_t)(i0 + wm * 32 + mi * 16) * S_
                                + j0 + wn * 64 + ni * 16,
                    acc[mi][ni], S_, wmma::mem_row_major);
    } else {
        // Two-phase epilogue: stage 128x64 halves in smem, gather-shift BD.
        const float* bd = g_bd + base;
        float* stage = sbuf;   // 128*68 = 8704 floats
#pragma unroll
        for (int half = 0; half < 2; half++) {
            if (wn == half) {
#pragma unroll
                for (int mi = 0; mi < 2; mi++)
#pragma unroll
                    for (int ni = 0; ni < 4; ni++)
                        wmma::store_matrix_sync(
                            &stage[(wm * 32 + mi * 16) * 68 + ni * 16],
                            acc[mi][ni], 68, wmma::mem_row_major);
            }
            __syncthreads();
#pragma unroll
            for (int l = 0; l < 32; l++) {
                int idx = tid + l * 256;
                int r = idx >> 6, cl = idx & 63;
                int ii = i0 + r, jj = j0 + half * 64 + cl;
                float ac = stage[r * 68 + cl];
                float bdv;
                if (jj <= ii)          bdv = bd[(size_t)ii * S_ + (S_ - 1 + jj - ii)];
                else if (jj == ii + 1) bdv = 0.f;
                else                   bdv = bd[(size_t)(ii + 1) * S_ + (jj - ii - 2)];
                g_sc[base + (size_t)ii * S_ + jj] = 0.125f * (ac + bdv);
            }
            __syncthreads();
        }
    }
}

// ============================================================
// Row softmax over j (2048) for every (b,h,i) row. In place.
// ============================================================
__global__ __launch_bounds__(256) void softmax_k()
{
    __shared__ float red[8];
    float* p = g_sc + (size_t)blockIdx.x * S_;
    int tid = threadIdx.x;
    float v[8];
    float m = -1e30f;
#pragma unroll
    for (int l = 0; l < 8; l++) { v[l] = p[tid + l * 256]; m = fmaxf(m, v[l]); }
#pragma unroll
    for (int o = 16; o; o >>= 1) m = fmaxf(m, __shfl_xor_sync(0xffffffffu, m, o));
    if ((tid & 31) == 0) red[tid >> 5] = m;
    __syncthreads();
    float mm = red[0];
#pragma unroll
    for (int w = 1; w < 8; w++) mm = fmaxf(mm, red[w]);
    __syncthreads();
    float s = 0.f;
#pragma unroll
    for (int l = 0; l < 8; l++) { v[l] = __expf(v[l] - mm); s += v[l]; }
#pragma unroll
    for (int o = 16; o; o >>= 1) s += __shfl_xor_sync(0xffffffffu, s, o);
    if ((tid & 31) == 0) red[tid >> 5] = s;
    __syncthreads();
    float tot = 0.f;
#pragma unroll
    for (int w = 0; w < 8; w++) tot += red[w];
    float inv = 1.f / tot;
#pragma unroll
    for (int l = 0; l < 8; l++) p[tid + l * 256] = v[l] * inv;
}

// ============================================================
// PV: attn_vec = P @ V per (b,h). Tile 128 x 64, K chunks of 32.
// ============================================================
__global__ __launch_bounds__(256) void wpv()
{
    __shared__ float As[128 * 36];   // P tile [128][32]
    __shared__ float Bs[32 * 68];    // V tile [32][64]
    int bh = blockIdx.y, b = bh >> 4, h = bh & 15;
    const float* P = g_sc + (size_t)bh * S_ * S_;
    const float* V = g_qkv + b * QLD_ + 2048 + h * 64;

    int tid = threadIdx.x;
    int w = tid >> 5, wm = w >> 1, wn = w & 1;
    int i0 = blockIdx.x * 128;

    frC acc[2][2];
#pragma unroll
    for (int mi = 0; mi < 2; mi++)
#pragma unroll
        for (int ni = 0; ni < 2; ni++) wmma::fill_fragment(acc[mi][ni], 0.f);

    for (int kk = 0; kk < S_; kk += 32) {
#pragma unroll
        for (int l = 0; l < 4; l++) {
            int idx = tid + l * 256;
            int r = idx >> 3, c4 = (idx & 7) << 2;
            float4 v = *(const float4*)(P + (size_t)(i0 + r) * S_ + kk + c4);
            As[r * 36 + c4 + 0] = t32(v.x); As[r * 36 + c4 + 1] = t32(v.y);
            As[r * 36 + c4 + 2] = t32(v.z); As[r * 36 + c4 + 3] = t32(v.w);
        }
#pragma unroll
        for (int l = 0; l < 2; l++) {
            int idx = tid + l * 256;
            int r = idx >> 4, c4 = (idx & 15) << 2;
            float4 v = *(const float4*)(V + (size_t)(kk + r) * ARS_ + c4);
            Bs[r * 68 + c4 + 0] = t32(v.x); Bs[r * 68 + c4 + 1] = t32(v.y);
            Bs[r * 68 + c4 + 2] = t32(v.z); Bs[r * 68 + c4 + 3] = t32(v.w);
        }
        __syncthreads();
#pragma unroll
        for (int k8 = 0; k8 < 4; k8++) {
            frA a[2];
#pragma unroll
            for (int mi = 0; mi < 2; mi++)
                wmma::load_matrix_sync(a[mi], &As[(wm * 32 + mi * 16) * 36 + k8 * 8], 36);
#pragma unroll
            for (int ni = 0; ni < 2; ni++) {
                frBr bf;
                wmma::load_matrix_sync(bf, &Bs[(k8 * 8) * 68 + wn * 32 + ni * 16], 68);
#pragma unroll
                for (int mi = 0; mi < 2; mi++)
                    wmma::mma_sync(acc[mi][ni], a[mi], bf, acc[mi][ni]);
            }
        }
        __syncthreads();
    }
#pragma unroll
    for (int mi = 0; mi < 2; mi++)
#pragma unroll
        for (int ni = 0; ni < 2; ni++)
            wmma::store_matrix_sync(
                g_att + ((size_t)(i0 + wm * 32 + mi * 16) * B_ + b) * D_
                      + h * 64 + wn * 32 + ni * 16,
                acc[mi][ni], B_ * D_, wmma::mem_row_major);
}

// ============================================================
// LayerNorm over D=1024 per row; writes final output.
// ============================================================
__global__ __launch_bounds__(256) void ln_k(const float* __restrict__ gamma,
                                            const float* __restrict__ beta,
                                            float* __restrict__ out)
{
    __shared__ float reds[8], redq[8];
    const float* y = g_y + (size_t)blockIdx.x * D_;
    int tid = threadIdx.x;
    float v[4];
    float s = 0.f, q = 0.f;
#pragma unroll
    for (int l = 0; l < 4; l++) {
        v[l] = y[tid + l * 256];
        s += v[l];
        q += v[l] * v[l];
    }
#pragma unroll
    for (int o = 16; o; o >>= 1) {
        s += __shfl_xor_sync(0xffffffffu, s, o);
        q += __shfl_xor_sync(0xffffffffu, q, o);
    }
    if ((tid & 31) == 0) { reds[tid >> 5] = s; redq[tid >> 5] = q; }
    __syncthreads();
    float ts = 0.f, tq = 0.f;
#pragma unroll
    for (int w = 0; w < 8; w++) { ts += reds[w]; tq += redq[w]; }
    float mu = ts * (1.f / 1024.f);
    float var = tq * (1.f / 1024.f) - mu * mu;
    float inv = rsqrtf(var + 1e-5f);
    float* o = out + (size_t)blockIdx.x * D_;
#pragma unroll
    for (int l = 0; l < 4; l++) {
        int c = tid + l * 256;
        o[c] = (v[l] - mu) * inv * gamma[c] + beta[c];
    }
}

// ============================================================
extern "C" void kernel_launch(void* const* d_in, const int* in_sizes, int n_in,
                              void* d_out, int out_size)
{
    const float* x    = (const float*)d_in[0];
    const float* pe   = (const float*)d_in[1];
    const float* pbu  = (const float*)d_in[2];
    const float* pbv  = (const float*)d_in[3];
    const float* Wqkv = (const float*)d_in[4];
    const float* Wrel = (const float*)d_in[5];
    const float* Wo   = (const float*)d_in[6];
    const float* gam  = (const float*)d_in[7];
    const float* bet  = (const float*)d_in[8];
    float* out = (float*)d_out;

    // 1) qkv = x @ W_qkv                [4096,1024]x[1024,3072]
    wgemm_nn<0><<<dim3(24, 32), 256>>>(x, Wqkv, nullptr, 4096, 3072, 1024);
    // 2) r = pos_emb @ W_relemb         [2048,1024]x[1024,1024]
    wgemm_nn<1><<<dim3(8, 16), 256>>>(pe, Wrel, nullptr, 2048, 1024, 1024);
    // 3) Draw = (q + v_bias) @ r^T  per (b,h)
    wscore<0><<<dim3(16, 16, 32), 256>>>(pbv);
    // 4) score = scale * ((q + u_bias) @ k^T + rel_shift(Draw))
    wscore<1><<<dim3(16, 16, 32), 256>>>(pbu);
    // 5) softmax over j
    softmax_k<<<BH_ * S_, 256>>>();
    // 6) attn_vec = P @ V per (b,h)
    wpv<<<dim3(16, 32), 256>>>();
    // 7) y = x + attn_vec @ W_o
    wgemm_nn<2><<<dim3(8, 32), 256>>>(nullptr, Wo, x, 4096, 1024, 1024);
    // 8) layernorm -> out
    ln_k<<<4096, 256>>>(gam, bet, out);
}

// round 3
// speedup vs baseline: 1.9313x; 1.9313x over previous
#include <cuda_runtime.h>
#include <stdint.h>

#define S_    2048
#define B_    2
#define D_    1024
#define H_    16
#define BH_   32
#define ROWS_ 4096
#define QLD_  3072
#define ARS_  6144   // B_*QLD_ : stride between seq rows in g_qkv

// ---- scratch (static device globals; no allocation) ----
__device__ float g_qkv[(size_t)ROWS_ * 3072];          // [s*B+b][q|k|v]
__device__ float g_r  [(size_t)S_ * D_];               // [t][h*64+d]
__device__ float g_bd [(size_t)BH_ * S_ * S_];         // Draw per (b,h)
__device__ float g_att[(size_t)ROWS_ * D_];            // attn_vec
__device__ float g_y  [(size_t)ROWS_ * D_];            // x + attn_out

// ---------------- mma / cp.async helpers ----------------
__device__ __forceinline__ void mma8(float* d, const uint32_t* a,
                                     const uint32_t* b, const float* c) {
    asm volatile(
        "mma.sync.aligned.m16n8k8.row.col.f32.tf32.tf32.f32 "
        "{%0,%1,%2,%3}, {%4,%5,%6,%7}, {%8,%9}, {%10,%11,%12,%13};\n"
        : "=f"(d[0]), "=f"(d[1]), "=f"(d[2]), "=f"(d[3])
        : "r"(a[0]), "r"(a[1]), "r"(a[2]), "r"(a[3]), "r"(b[0]), "r"(b[1]),
          "f"(c[0]), "f"(c[1]), "f"(c[2]), "f"(c[3]));
}
__device__ __forceinline__ uint32_t f2u(float x) { return __float_as_uint(x); }
__device__ __forceinline__ void cpa16(uint32_t s, const void* g) {
    asm volatile("cp.async.cg.shared.global [%0], [%1], 16;\n" :: "r"(s), "l"(g));
}
__device__ __forceinline__ void cpcommit() { asm volatile("cp.async.commit_group;\n"); }
template <int N> __device__ __forceinline__ void cpwait() {
    asm volatile("cp.async.wait_group %0;\n" :: "n"(N));
}

// ============================================================
// Projection GEMM, K=1024 fixed, tile 128x128x32, cp.async 2-stage.
// MODE 0: g_qkv = A@B   1: g_r = A@B   2: g_y = g_att@B + Xres
// ============================================================
template <int MODE>
__global__ __launch_bounds__(256) void pgemm(const float* __restrict__ A,
                                             const float* __restrict__ Bw,
                                             const float* __restrict__ Xres,
                                             int N)
{
    extern __shared__ float sm[];
    float* As = sm;               // 2 x 128 x 36
    float* Bs = sm + 9216;        // 2 x 32  x 136
    const float* Ap = (MODE == 2) ? (const float*)g_att : A;
    float* C = (MODE == 0) ? g_qkv : (MODE == 1) ? g_r : g_y;

    int tid = threadIdx.x, l = tid & 31, w = tid >> 5, wm = w >> 1, wn = w & 1;
    size_t m0 = (size_t)blockIdx.y * 128, n0 = (size_t)blockIdx.x * 128;
    uint32_t sA = (uint32_t)__cvta_generic_to_shared(As);
    uint32_t sB = (uint32_t)__cvta_generic_to_shared(Bs);

    float acc[2][8][4] = {};

#define STAGE(IT, BUF)                                                          \
    {                                                                           \
        int kk = (IT) * 32;                                                     \
        uint32_t ab = sA + (BUF) * 4608 * 4;                                    \
        _Pragma("unroll")                                                       \
        for (int t = 0; t < 4; t++) {                                           \
            int idx = tid + t * 256; int r = idx >> 3, c4 = (idx & 7) << 2;     \
            cpa16(ab + (r * 36 + c4) * 4, Ap + (m0 + r) * 1024 + kk + c4);      \
        }                                                                       \
        uint32_t bb = sB + (BUF) * 4352 * 4;                                    \
        _Pragma("unroll")                                                       \
        for (int t = 0; t < 4; t++) {                                           \
            int idx = tid + t * 256; int r = idx >> 5, c4 = (idx & 31) << 2;    \
            cpa16(bb + (r * 136 + c4) * 4, Bw + (size_t)(kk + r) * N + n0 + c4);\
        }                                                                       \
        cpcommit();                                                             \
    }

    STAGE(0, 0);
    for (int it = 0; it < 32; it++) {
        int buf = it & 1;
        if (it + 1 < 32) { STAGE(it + 1, buf ^ 1); cpwait<1>(); }
        else             { cpwait<0>(); }
        __syncthreads();
        const float* As_ = As + buf * 4608;
        const float* Bs_ = Bs + buf * 4352;
#pragma unroll
        for (int k8 = 0; k8 < 4; k8++) {
            uint32_t a[2][4];
#pragma unroll
            for (int mt = 0; mt < 2; mt++) {
                int r = wm * 32 + mt * 16 + (l >> 2);
                a[mt][0] = f2u(As_[r * 36 + k8 * 8 + (l & 3)]);
                a[mt][1] = f2u(As_[(r + 8) * 36 + k8 * 8 + (l & 3)]);
                a[mt][2] = f2u(As_[r * 36 + k8 * 8 + (l & 3) + 4]);
                a[mt][3] = f2u(As_[(r + 8) * 36 + k8 * 8 + (l & 3) + 4]);
            }
#pragma unroll
            for (int nt = 0; nt < 8; nt++) {
                uint32_t bf[2];
                int cb = wn * 64 + nt * 8 + (l >> 2);
                bf[0] = f2u(Bs_[(k8 * 8 + (l & 3)) * 136 + cb]);
                bf[1] = f2u(Bs_[(k8 * 8 + (l & 3) + 4) * 136 + cb]);
#pragma unroll
                for (int mt = 0; mt < 2; mt++)
                    mma8(acc[mt][nt], a[mt], bf, acc[mt][nt]);
            }
        }
        __syncthreads();
    }
#undef STAGE

#pragma unroll
    for (int mt = 0; mt < 2; mt++) {
        size_t r0 = m0 + wm * 32 + mt * 16 + (l >> 2);
#pragma unroll
        for (int nt = 0; nt < 8; nt++) {
            size_t c = n0 + wn * 64 + nt * 8 + 2 * (l & 3);
            float2 v0 = make_float2(acc[mt][nt][0], acc[mt][nt][1]);
            float2 v1 = make_float2(acc[mt][nt][2], acc[mt][nt][3]);
            if (MODE == 2) {
                float2 x0 = *(const float2*)(Xres + r0 * N + c);
                float2 x1 = *(const float2*)(Xres + (r0 + 8) * N + c);
                v0.x += x0.x; v0.y += x0.y; v1.x += x1.x; v1.y += x1.y;
            }
            *(float2*)(C + r0 * N + c) = v0;
            *(float2*)(C + (r0 + 8) * N + c) = v1;
        }
    }
}

// ============================================================
// Draw = (q + pos_bias_v) @ r^T per (b,h). 128x128, K=64.
// ============================================================
__global__ __launch_bounds__(256) void bd_gemm(const float* __restrict__ pbv)
{
    extern __shared__ float sm[];
    float* Qs = sm;               // 128 x 68
    float* Rs = sm + 128 * 68;    // 128 x 68
    int tid = threadIdx.x, l = tid & 31, w = tid >> 5;
    int bh = blockIdx.z, b = bh >> 4, h = bh & 15;
    int i0 = blockIdx.y * 128, t0 = blockIdx.x * 128;
    const float* Qg = g_qkv + (size_t)b * QLD_ + h * 64;
    const float* Rg = g_r + h * 64;
    const float* bias = pbv + h * 64;

#pragma unroll
    for (int t = 0; t < 8; t++) {
        int idx = tid + t * 256; int r = idx >> 4, c4 = (idx & 15) << 2;
        float4 a4 = *(const float4*)(Qg + (size_t)(i0 + r) * ARS_ + c4);
        float4 u4 = *(const float4*)(bias + c4);
        a4.x += u4.x; a4.y += u4.y; a4.z += u4.z; a4.w += u4.w;
        *(float4*)&Qs[r * 68 + c4] = a4;
        *(float4*)&Rs[r * 68 + c4] = *(const float4*)(Rg + (size_t)(t0 + r) * D_ + c4);
    }
    __syncthreads();

    uint32_t qa[8][4];
    int ar = w * 16 + (l >> 2);
#pragma unroll
    for (int k8 = 0; k8 < 8; k8++) {
        qa[k8][0] = f2u(Qs[ar * 68 + k8 * 8 + (l & 3)]);
        qa[k8][1] = f2u(Qs[(ar + 8) * 68 + k8 * 8 + (l & 3)]);
        qa[k8][2] = f2u(Qs[ar * 68 + k8 * 8 + (l & 3) + 4]);
        qa[k8][3] = f2u(Qs[(ar + 8) * 68 + k8 * 8 + (l & 3) + 4]);
    }
    float acc[16][4] = {};
#pragma unroll
    for (int k8 = 0; k8 < 8; k8++)
#pragma unroll
        for (int nt = 0; nt < 16; nt++) {
            uint32_t bf[2];
            int kr = nt * 8 + (l >> 2);
            bf[0] = f2u(Rs[kr * 68 + k8 * 8 + (l & 3)]);
            bf[1] = f2u(Rs[kr * 68 + k8 * 8 + (l & 3) + 4]);
            mma8(acc[nt], qa[k8], bf, acc[nt]);
        }

    float* out = g_bd + (size_t)bh * S_ * S_;
    int gr = i0 + w * 16 + (l >> 2);
#pragma unroll
    for (int nt = 0; nt < 16; nt++) {
        int gc = t0 + nt * 8 + 2 * (l & 3);
        *(float2*)(out + (size_t)gr * S_ + gc)       = make_float2(acc[nt][0], acc[nt][1]);
        *(float2*)(out + (size_t)(gr + 8) * S_ + gc) = make_float2(acc[nt][2], acc[nt][3]);
    }
}

// ============================================================
// Fused attention: AC GEMM + rel-shift BD + online softmax + PV.
// One CTA = 128 q-rows of one (b,h). Each warp owns 16 rows.
// ============================================================
__device__ __forceinline__ float bdval(const float* bd, int i, int j)
{
    if (j <= i)      return __ldg(bd + (size_t)i * S_ + (S_ - 1 + j - i));
    if (j == i + 1)  return 0.f;
    return __ldg(bd + (size_t)(i + 1) * S_ + (j - i - 2));
}

__global__ __launch_bounds__(256) void fattn(const float* __restrict__ pbu)
{
    extern __shared__ float sm[];
    float* Qs = sm;                    // 128 x 68
    float* Ks = Qs + 128 * 68;         // 128 x 68
    float* Vs = Ks + 128 * 68;         // 128 x 72
    float* Ps = Vs + 128 * 72;         // 128 x 132
    int tid = threadIdx.x, l = tid & 31, w = tid >> 5;
    int bh = blockIdx.y, b = bh >> 4, h = bh & 15;
    int i0 = blockIdx.x * 128;
    const float* Qg = g_qkv + (size_t)b * QLD_ + h * 64;
    const float* Kg = Qg + 1024;
    const float* Vg = Qg + 2048;
    const float* bd = g_bd + (size_t)bh * S_ * S_;
    const float* bias = pbu + h * 64;
    uint32_t sK = (uint32_t)__cvta_generic_to_shared(Ks);
    uint32_t sV = (uint32_t)__cvta_generic_to_shared(Vs);

    // Q + bias_u -> smem
#pragma unroll
    for (int t = 0; t < 8; t++) {
        int idx = tid + t * 256; int r = idx >> 4, c4 = (idx & 15) << 2;
        float4 a4 = *(const float4*)(Qg + (size_t)(i0 + r) * ARS_ + c4);
        float4 u4 = *(const float4*)(bias + c4);
        a4.x += u4.x; a4.y += u4.y; a4.z += u4.z; a4.w += u4.w;
        *(float4*)&Qs[r * 68 + c4] = a4;
    }
    // prefetch K0 (group), V0 (group)
#pragma unroll
    for (int t = 0; t < 8; t++) {
        int idx = tid + t * 256; int r = idx >> 4, c4 = (idx & 15) << 2;
        cpa16(sK + (r * 68 + c4) * 4, Kg + (size_t)r * ARS_ + c4);
    }
    cpcommit();
#pragma unroll
    for (int t = 0; t < 8; t++) {
        int idx = tid + t * 256; int r = idx >> 4, c4 = (idx & 15) << 2;
        cpa16(sV + (r * 72 + c4) * 4, Vg + (size_t)r * ARS_ + c4);
    }
    cpcommit();
    __syncthreads();   // Qs ready

    uint32_t qa[8][4];
    int lr0 = w * 16 + (l >> 2);
#pragma unroll
    for (int k8 = 0; k8 < 8; k8++) {
        qa[k8][0] = f2u(Qs[lr0 * 68 + k8 * 8 + (l & 3)]);
        qa[k8][1] = f2u(Qs[(lr0 + 8) * 68 + k8 * 8 + (l & 3)]);
        qa[k8][2] = f2u(Qs[lr0 * 68 + k8 * 8 + (l & 3) + 4]);
        qa[k8][3] = f2u(Qs[(lr0 + 8) * 68 + k8 * 8 + (l & 3) + 4]);
    }

    float o[8][4] = {};
    float m0 = -1e30f, m1 = -1e30f, l0 = 0.f, l1 = 0.f;
    int row0 = i0 + lr0, row1 = row0 + 8;

    for (int it = 0; it < 16; it++) {
        int j0 = it * 128;
        cpwait<1>();              // K(it) done (V(it) may be pending)
        __syncthreads();

        // ---- AC = (q+u) . k^T ----
        float acc[16][4] = {};
#pragma unroll
        for (int k8 = 0; k8 < 8; k8++)
#pragma unroll
            for (int nt = 0; nt < 16; nt++) {
                uint32_t bf[2];
                int kr = nt * 8 + (l >> 2);
                bf[0] = f2u(Ks[kr * 68 + k8 * 8 + (l & 3)]);
                bf[1] = f2u(Ks[kr * 68 + k8 * 8 + (l & 3) + 4]);
                mma8(acc[nt], qa[k8], bf, acc[nt]);
            }

        // ---- add rel-shifted BD, scale, row max ----
        float mx0 = -1e30f, mx1 = -1e30f;
#pragma unroll
        for (int nt = 0; nt < 16; nt++) {
            int c0 = j0 + nt * 8 + 2 * (l & 3);
            float s;
            s = 0.125f * (acc[nt][0] + bdval(bd, row0, c0));     acc[nt][0] = s; mx0 = fmaxf(mx0, s);
            s = 0.125f * (acc[nt][1] + bdval(bd, row0, c0 + 1)); acc[nt][1] = s; mx0 = fmaxf(mx0, s);
            s = 0.125f * (acc[nt][2] + bdval(bd, row1, c0));     acc[nt][2] = s; mx1 = fmaxf(mx1, s);
            s = 0.125f * (acc[nt][3] + bdval(bd, row1, c0 + 1)); acc[nt][3] = s; mx1 = fmaxf(mx1, s);
        }
        mx0 = fmaxf(mx0, __shfl_xor_sync(0xffffffffu, mx0, 1));
        mx0 = fmaxf(mx0, __shfl_xor_sync(0xffffffffu, mx0, 2));
        mx1 = fmaxf(mx1, __shfl_xor_sync(0xffffffffu, mx1, 1));
        mx1 = fmaxf(mx1, __shfl_xor_sync(0xffffffffu, mx1, 2));
        float mn0 = fmaxf(m0, mx0), mn1 = fmaxf(m1, mx1);
        float al0 = __expf(m0 - mn0), al1 = __expf(m1 - mn1);
        m0 = mn0; m1 = mn1;

        float rs0 = 0.f, rs1 = 0.f;
#pragma unroll
        for (int nt = 0; nt < 16; nt++) {
            float p0 = __expf(acc[nt][0] - mn0), p1 = __expf(acc[nt][1] - mn0);
            float p2 = __expf(acc[nt][2] - mn1), p3 = __expf(acc[nt][3] - mn1);
            rs0 += p0 + p1; rs1 += p2 + p3;
            int c = nt * 8 + 2 * (l & 3);
            *(float2*)&Ps[lr0 * 132 + c]       = make_float2(p0, p1);
            *(float2*)&Ps[(lr0 + 8) * 132 + c] = make_float2(p2, p3);
        }
        rs0 += __shfl_xor_sync(0xffffffffu, rs0, 1);
        rs0 += __shfl_xor_sync(0xffffffffu, rs0, 2);
        rs1 += __shfl_xor_sync(0xffffffffu, rs1, 1);
        rs1 += __shfl_xor_sync(0xffffffffu, rs1, 2);
        l0 = l0 * al0 + rs0;
        l1 = l1 * al1 + rs1;
#pragma unroll
        for (int nt2 = 0; nt2 < 8; nt2++) {
            o[nt2][0] *= al0; o[nt2][1] *= al0; o[nt2][2] *= al1; o[nt2][3] *= al1;
        }
        __syncthreads();          // done reading Ks; Ps written

        if (it + 1 < 16) {        // prefetch K(it+1) into freed buffer
            const float* kb = Kg + (size_t)((it + 1) * 128) * ARS_;
#pragma unroll
            for (int t = 0; t < 8; t++) {
                int idx = tid + t * 256; int r = idx >> 4, c4 = (idx & 15) << 2;
                cpa16(sK + (r * 68 + c4) * 4, kb + (size_t)r * ARS_ + c4);
            }
            cpcommit();
            cpwait<1>();          // V(it) done (K(it+1) pending)
        } else {
            cpwait<0>();          // V(15) done
        }
        __syncthreads();          // Vs(it) visible

        // ---- PV: O += P . V ----
#pragma unroll
        for (int k8 = 0; k8 < 16; k8++) {
            uint32_t pa[4];
            pa[0] = f2u(Ps[lr0 * 132 + k8 * 8 + (l & 3)]);
            pa[1] = f2u(Ps[(lr0 + 8) * 132 + k8 * 8 + (l & 3)]);
            pa[2] = f2u(Ps[lr0 * 132 + k8 * 8 + (l & 3) + 4]);
            pa[3] = f2u(Ps[(lr0 + 8) * 132 + k8 * 8 + (l & 3) + 4]);
#pragma unroll
            for (int nt2 = 0; nt2 < 8; nt2++) {
                uint32_t vb[2];
                int kr = k8 * 8 + (l & 3);
                vb[0] = f2u(Vs[kr * 72 + nt2 * 8 + (l >> 2)]);
                vb[1] = f2u(Vs[(kr + 4) * 72 + nt2 * 8 + (l >> 2)]);
                mma8(o[nt2], pa, vb, o[nt2]);
            }
        }
        __syncthreads();          // done reading Vs

        if (it + 1 < 16) {        // prefetch V(it+1)
            const float* vg = Vg + (size_t)((it + 1) * 128) * ARS_;
#pragma unroll
            for (int t = 0; t < 8; t++) {
                int idx = tid + t * 256; int r = idx >> 4, c4 = (idx & 15) << 2;
                cpa16(sV + (r * 72 + c4) * 4, vg + (size_t)r * ARS_ + c4);
            }
            cpcommit();
        }
    }

    float inv0 = 1.f / l0, inv1 = 1.f / l1;
#pragma unroll
    for (int nt2 = 0; nt2 < 8; nt2++) {
        int c = h * 64 + nt2 * 8 + 2 * (l & 3);
        *(float2*)(g_att + ((size_t)row0 * B_ + b) * D_ + c) =
            make_float2(o[nt2][0] * inv0, o[nt2][1] * inv0);
        *(float2*)(g_att + ((size_t)row1 * B_ + b) * D_ + c) =
            make_float2(o[nt2][2] * inv1, o[nt2][3] * inv1);
    }
}

// ============================================================
// LayerNorm over D=1024 per row.
// ============================================================
__global__ __launch_bounds__(256) void ln_k(const float* __restrict__ gamma,
                                            const float* __restrict__ beta,
                                            float* __restrict__ out)
{
    __shared__ float reds[8], redq[8];
    const float* y = g_y + (size_t)blockIdx.x * D_;
    int tid = threadIdx.x;
    float v[4];
    float s = 0.f, q = 0.f;
#pragma unroll
    for (int t = 0; t < 4; t++) {
        v[t] = y[tid + t * 256];
        s += v[t]; q += v[t] * v[t];
    }
#pragma unroll
    for (int o = 16; o; o >>= 1) {
        s += __shfl_xor_sync(0xffffffffu, s, o);
        q += __shfl_xor_sync(0xffffffffu, q, o);
    }
    if ((tid & 31) == 0) { reds[tid >> 5] = s; redq[tid >> 5] = q; }
    __syncthreads();
    float ts = 0.f, tq = 0.f;
#pragma unroll
    for (int wv = 0; wv < 8; wv++) { ts += reds[wv]; tq += redq[wv]; }
    float mu = ts * (1.f / 1024.f);
    float var = tq * (1.f / 1024.f) - mu * mu;
    float inv = rsqrtf(var + 1e-5f);
    float* op = out + (size_t)blockIdx.x * D_;
#pragma unroll
    for (int t = 0; t < 4; t++) {
        int c = tid + t * 256;
        op[c] = (v[t] - mu) * inv * gamma[c] + beta[c];
    }
}

// ============================================================
extern "C" void kernel_launch(void* const* d_in, const int* in_sizes, int n_in,
                              void* d_out, int out_size)
{
    const float* x    = (const float*)d_in[0];
    const float* pe   = (const float*)d_in[1];
    const float* pbu  = (const float*)d_in[2];
    const float* pbv  = (const float*)d_in[3];
    const float* Wqkv = (const float*)d_in[4];
    const float* Wrel = (const float*)d_in[5];
    const float* Wo   = (const float*)d_in[6];
    const float* gam  = (const float*)d_in[7];
    const float* bet  = (const float*)d_in[8];
    float* out = (float*)d_out;

    const int PG_SMEM = 71680;     // (9216 + 8704) * 4
    const int BD_SMEM = 69632;     // 2 * 128*68 * 4
    const int FA_SMEM = 174080;    // 128*(68+68+72+132) * 4
    cudaFuncSetAttribute(pgemm<0>, cudaFuncAttributeMaxDynamicSharedMemorySize, PG_SMEM);
    cudaFuncSetAttribute(pgemm<1>, cudaFuncAttributeMaxDynamicSharedMemorySize, PG_SMEM);
    cudaFuncSetAttribute(pgemm<2>, cudaFuncAttributeMaxDynamicSharedMemorySize, PG_SMEM);
    cudaFuncSetAttribute(bd_gemm,  cudaFuncAttributeMaxDynamicSharedMemorySize, BD_SMEM);
    cudaFuncSetAttribute(fattn,    cudaFuncAttributeMaxDynamicSharedMemorySize, FA_SMEM);

    // 1) qkv = x @ W_qkv
    pgemm<0><<<dim3(24, 32), 256, PG_SMEM>>>(x, Wqkv, nullptr, 3072);
    // 2) r = pos_emb @ W_relemb
    pgemm<1><<<dim3(8, 16), 256, PG_SMEM>>>(pe, Wrel, nullptr, 1024);
    // 3) Draw = (q + pbv) @ r^T per (b,h)
    bd_gemm<<<dim3(16, 16, 32), 256, BD_SMEM>>>(pbv);
    // 4) fused: scores + rel-shift + softmax + PV
    fattn<<<dim3(16, 32), 256, FA_SMEM>>>(pbu);
    // 5) y = x + attn_vec @ W_o
    pgemm<2><<<dim3(8, 32), 256, PG_SMEM>>>(nullptr, Wo, x, 1024);
    // 6) layernorm
    ln_k<<<4096, 256>>>(gam, bet, out);
}

// round 4
// speedup vs baseline: 2.8044x; 1.4521x over previous
#include <cuda_runtime.h>
#include <stdint.h>

#define S_    2048
#define B_    2
#define D_    1024
#define H_    16
#define BH_   32
#define ROWS_ 4096
#define QLD_  3072
#define ARS_  6144   // B_*QLD_ : stride between seq rows in g_qkv

// ---- scratch (static device globals; no allocation) ----
__device__ float g_qkv[(size_t)ROWS_ * 3072];          // [s*B+b][q|k|v]
__device__ float g_r  [(size_t)S_ * D_];               // [t][h*64+d]
__device__ float g_bd [(size_t)BH_ * S_ * S_];         // Draw per (b,h)
__device__ float g_att[(size_t)ROWS_ * D_];            // attn_vec
__device__ float g_y  [(size_t)ROWS_ * D_];            // x + attn_out

// ---------------- mma / cp.async / ldmatrix helpers ----------------
__device__ __forceinline__ void mma8(float* d, const uint32_t* a,
                                     const uint32_t* b, const float* c) {
    asm volatile(
        "mma.sync.aligned.m16n8k8.row.col.f32.tf32.tf32.f32 "
        "{%0,%1,%2,%3}, {%4,%5,%6,%7}, {%8,%9}, {%10,%11,%12,%13};\n"
        : "=f"(d[0]), "=f"(d[1]), "=f"(d[2]), "=f"(d[3])
        : "r"(a[0]), "r"(a[1]), "r"(a[2]), "r"(a[3]), "r"(b[0]), "r"(b[1]),
          "f"(c[0]), "f"(c[1]), "f"(c[2]), "f"(c[3]));
}
__device__ __forceinline__ uint32_t f2u(float x) { return __float_as_uint(x); }
__device__ __forceinline__ void cpa16(uint32_t s, const void* g) {
    asm volatile("cp.async.cg.shared.global [%0], [%1], 16;\n" :: "r"(s), "l"(g));
}
__device__ __forceinline__ void cpcommit() { asm volatile("cp.async.commit_group;\n"); }
template <int N> __device__ __forceinline__ void cpwait() {
    asm volatile("cp.async.wait_group %0;\n" :: "n"(N));
}
// ldmatrix.x4: four 8-row x 16-byte tiles; thread l of tile t gets
// (row l>>2, f32 elem l&3) -> exactly the m16n8k8 tf32 fragment layout.
__device__ __forceinline__ void ldsm4(uint32_t* r, uint32_t a) {
    asm volatile("ldmatrix.sync.aligned.m8n8.x4.shared.b16 {%0,%1,%2,%3}, [%4];\n"
        : "=r"(r[0]), "=r"(r[1]), "=r"(r[2]), "=r"(r[3]) : "r"(a));
}
__device__ __forceinline__ float ex2(float x) {
    float y; asm("ex2.approx.f32 %0, %1;" : "=f"(y) : "f"(x)); return y;
}

// ============================================================
// Projection GEMM, K=1024 fixed, tile 128x128x32, cp.async 2-stage.
// MODE 0: g_qkv = A@B   1: g_r = A@B   2: g_y = g_att@B + Xres
// ============================================================
template <int MODE>
__global__ __launch_bounds__(256) void pgemm(const float* __restrict__ A,
                                             const float* __restrict__ Bw,
                                             const float* __restrict__ Xres,
                                             int N)
{
    extern __shared__ float sm[];
    float* As = sm;               // 2 x 128 x 36
    float* Bs = sm + 9216;        // 2 x 32  x 136
    const float* Ap = (MODE == 2) ? (const float*)g_att : A;
    float* C = (MODE == 0) ? g_qkv : (MODE == 1) ? g_r : g_y;

    int tid = threadIdx.x, l = tid & 31, w = tid >> 5, wm = w >> 1, wn = w & 1;
    size_t m0 = (size_t)blockIdx.y * 128, n0 = (size_t)blockIdx.x * 128;
    uint32_t sA = (uint32_t)__cvta_generic_to_shared(As);
    uint32_t sB = (uint32_t)__cvta_generic_to_shared(Bs);

    float acc[2][8][4] = {};

#define STAGE(IT, BUF)                                                          \
    {                                                                           \
        int kk = (IT) * 32;                                                     \
        uint32_t ab = sA + (BUF) * 4608 * 4;                                    \
        _Pragma("unroll")                                                       \
        for (int t = 0; t < 4; t++) {                                           \
            int idx = tid + t * 256; int r = idx >> 3, c4 = (idx & 7) << 2;     \
            cpa16(ab + (r * 36 + c4) * 4, Ap + (m0 + r) * 1024 + kk + c4);      \
        }                                                                       \
        uint32_t bb = sB + (BUF) * 4352 * 4;                                    \
        _Pragma("unroll")                                                       \
        for (int t = 0; t < 4; t++) {                                           \
            int idx = tid + t * 256; int r = idx >> 5, c4 = (idx & 31) << 2;    \
            cpa16(bb + (r * 136 + c4) * 4, Bw + (size_t)(kk + r) * N + n0 + c4);\
        }                                                                       \
        cpcommit();                                                             \
    }

    STAGE(0, 0);
    for (int it = 0; it < 32; it++) {
        int buf = it & 1;
        if (it + 1 < 32) { STAGE(it + 1, buf ^ 1); cpwait<1>(); }
        else             { cpwait<0>(); }
        __syncthreads();
        const float* As_ = As + buf * 4608;
        const float* Bs_ = Bs + buf * 4352;
#pragma unroll
        for (int k8 = 0; k8 < 4; k8++) {
            uint32_t a[2][4];
#pragma unroll
            for (int mt = 0; mt < 2; mt++) {
                int r = wm * 32 + mt * 16 + (l >> 2);
                a[mt][0] = f2u(As_[r * 36 + k8 * 8 + (l & 3)]);
                a[mt][1] = f2u(As_[(r + 8) * 36 + k8 * 8 + (l & 3)]);
                a[mt][2] = f2u(As_[r * 36 + k8 * 8 + (l & 3) + 4]);
                a[mt][3] = f2u(As_[(r + 8) * 36 + k8 * 8 + (l & 3) + 4]);
            }
#pragma unroll
            for (int nt = 0; nt < 8; nt++) {
                uint32_t bf[2];
                int cb = wn * 64 + nt * 8 + (l >> 2);
                bf[0] = f2u(Bs_[(k8 * 8 + (l & 3)) * 136 + cb]);
                bf[1] = f2u(Bs_[(k8 * 8 + (l & 3) + 4) * 136 + cb]);
#pragma unroll
                for (int mt = 0; mt < 2; mt++)
                    mma8(acc[mt][nt], a[mt], bf, acc[mt][nt]);
            }
        }
        __syncthreads();
    }
#undef STAGE

#pragma unroll
    for (int mt = 0; mt < 2; mt++) {
        size_t r0 = m0 + wm * 32 + mt * 16 + (l >> 2);
#pragma unroll
        for (int nt = 0; nt < 8; nt++) {
            size_t c = n0 + wn * 64 + nt * 8 + 2 * (l & 3);
            float2 v0 = make_float2(acc[mt][nt][0], acc[mt][nt][1]);
            float2 v1 = make_float2(acc[mt][nt][2], acc[mt][nt][3]);
            if (MODE == 2) {
                float2 x0 = *(const float2*)(Xres + r0 * N + c);
                float2 x1 = *(const float2*)(Xres + (r0 + 8) * N + c);
                v0.x += x0.x; v0.y += x0.y; v1.x += x1.x; v1.y += x1.y;
            }
            *(float2*)(C + r0 * N + c) = v0;
            *(float2*)(C + (r0 + 8) * N + c) = v1;
        }
    }
}

// ============================================================
// Draw = (q + pos_bias_v) @ r^T per (b,h). 128x128, K=64, ldmatrix.
// ============================================================
__global__ __launch_bounds__(256, 2) void bd_gemm(const float* __restrict__ pbv)
{
    extern __shared__ float sm[];
    float* Qs = sm;               // 128 x 68
    float* Rs = sm + 8704;        // 128 x 68
    int tid = threadIdx.x, l = tid & 31, w = tid >> 5;
    int bh = blockIdx.z, b = bh >> 4, h = bh & 15;
    int i0 = blockIdx.y * 128, t0 = blockIdx.x * 128;
    const float* Qg = g_qkv + (size_t)b * QLD_ + h * 64;
    const float* Rg = g_r + h * 64;
    const float* bias = pbv + h * 64;

#pragma unroll
    for (int t = 0; t < 8; t++) {
        int idx = tid + t * 256; int r = idx >> 4, c4 = (idx & 15) << 2;
        float4 a4 = *(const float4*)(Qg + (size_t)(i0 + r) * ARS_ + c4);
        float4 u4 = *(const float4*)(bias + c4);
        a4.x += u4.x; a4.y += u4.y; a4.z += u4.z; a4.w += u4.w;
        *(float4*)&Qs[r * 68 + c4] = a4;
        *(float4*)&Rs[r * 68 + c4] = *(const float4*)(Rg + (size_t)(t0 + r) * D_ + c4);
    }
    __syncthreads();

    uint32_t sQ = (uint32_t)__cvta_generic_to_shared(Qs);
    uint32_t sR = (uint32_t)__cvta_generic_to_shared(Rs);
    uint32_t aoff = ((w * 16 + ((l >> 3) & 1) * 8 + (l & 7)) * 68 + ((l >> 4) & 1) * 4) * 4;
    uint32_t boff = ((((l >> 4) & 1) * 8 + (l & 7)) * 68 + ((l >> 3) & 1) * 4) * 4;

    uint32_t qa[8][4];
#pragma unroll
    for (int k8 = 0; k8 < 8; k8++) ldsm4(qa[k8], sQ + aoff + k8 * 32);

    float acc[16][4] = {};
#pragma unroll
    for (int k8 = 0; k8 < 8; k8++)
#pragma unroll
        for (int np = 0; np < 8; np++) {
            uint32_t kb[4];
            ldsm4(kb, sR + boff + np * 16 * 272 + k8 * 32);
            mma8(acc[2 * np],     qa[k8], kb,     acc[2 * np]);
            mma8(acc[2 * np + 1], qa[k8], kb + 2, acc[2 * np + 1]);
        }

    float* out = g_bd + (size_t)bh * S_ * S_;
    int gr = i0 + w * 16 + (l >> 2);
#pragma unroll
    for (int nt = 0; nt < 16; nt++) {
        int gc = t0 + nt * 8 + 2 * (l & 3);
        *(float2*)(out + (size_t)gr * S_ + gc)       = make_float2(acc[nt][0], acc[nt][1]);
        *(float2*)(out + (size_t)(gr + 8) * S_ + gc) = make_float2(acc[nt][2], acc[nt][3]);
    }
}

// ============================================================
// Fused attention: AC GEMM + rel-shift BD + online softmax + PV.
// 64-col sub-chunks; Ps overlays Qs; 2 CTAs/SM.
// ============================================================
__device__ __forceinline__ float bdval(const float* bd, int i, int j)
{
    if (j <= i)      return __ldg(bd + (size_t)i * S_ + (S_ - 1 + j - i));
    if (j == i + 1)  return 0.f;
    return __ldg(bd + (size_t)(i + 1) * S_ + (j - i - 2));
}

__global__ __launch_bounds__(256, 2) void fattn(const float* __restrict__ pbu)
{
    extern __shared__ float sm[];
    float* Qs = sm;                    // 128 x 68 (overlaid by Ps after init)
    float* Ps = sm;                    // 128 x 68 (64 cols used)
    float* Ks = sm + 8704;             // 128 x 68
    float* Vs = sm + 17408;            // 128 x 72
    int tid = threadIdx.x, l = tid & 31, w = tid >> 5;
    int bh = blockIdx.y, b = bh >> 4, h = bh & 15;
    int i0 = blockIdx.x * 128;
    const float* Qg = g_qkv + (size_t)b * QLD_ + h * 64;
    const float* Kg = Qg + 1024;
    const float* Vg = Qg + 2048;
    const float* bd = g_bd + (size_t)bh * S_ * S_;
    const float* bias = pbu + h * 64;
    uint32_t sQ = (uint32_t)__cvta_generic_to_shared(Qs);
    uint32_t sK = (uint32_t)__cvta_generic_to_shared(Ks);
    uint32_t sV = (uint32_t)__cvta_generic_to_shared(Vs);

    // Q + bias_u -> smem (plain), prefetch K0, V0 (cp.async groups)
#pragma unroll
    for (int t = 0; t < 8; t++) {
        int idx = tid + t * 256; int r = idx >> 4, c4 = (idx & 15) << 2;
        float4 a4 = *(const float4*)(Qg + (size_t)(i0 + r) * ARS_ + c4);
        float4 u4 = *(const float4*)(bias + c4);
        a4.x += u4.x; a4.y += u4.y; a4.z += u4.z; a4.w += u4.w;
        *(float4*)&Qs[r * 68 + c4] = a4;
    }
#pragma unroll
    for (int t = 0; t < 8; t++) {
        int idx = tid + t * 256; int r = idx >> 4, c4 = (idx & 15) << 2;
        cpa16(sK + (r * 68 + c4) * 4, Kg + (size_t)r * ARS_ + c4);
    }
    cpcommit();
#pragma unroll
    for (int t = 0; t < 8; t++) {
        int idx = tid + t * 256; int r = idx >> 4, c4 = (idx & 15) << 2;
        cpa16(sV + (r * 72 + c4) * 4, Vg + (size_t)r * ARS_ + c4);
    }
    cpcommit();
    __syncthreads();    // Qs visible

    // fragment ldmatrix byte offsets
    uint32_t aoff = ((w * 16 + ((l >> 3) & 1) * 8 + (l & 7)) * 68 + ((l >> 4) & 1) * 4) * 4;
    uint32_t kboff = ((((l >> 4) & 1) * 8 + (l & 7)) * 68 + ((l >> 3) & 1) * 4) * 4;

    uint32_t qa[8][4];
#pragma unroll
    for (int k8 = 0; k8 < 8; k8++) ldsm4(qa[k8], sQ + aoff + k8 * 32);

    float o[8][4] = {};
    float mrow0 = -1e30f, mrow1 = -1e30f, lsum0 = 0.f, lsum1 = 0.f;
    int lr0 = w * 16 + (l >> 2);
    int row0 = i0 + lr0, row1 = row0 + 8;
    const float CS = 0.1803368801111204f;   // 0.125 * log2(e)

    for (int it = 0; it < 16; it++) {
        cpwait<1>();          // K(it) done (V(it) may be pending)
        __syncthreads();
#pragma unroll
        for (int half = 0; half < 2; half++) {
            // ---- AC = (q+u) . k^T  (64 j-cols) ----
            float acc[8][4] = {};
#pragma unroll
            for (int k8 = 0; k8 < 8; k8++)
#pragma unroll
                for (int np = 0; np < 4; np++) {
                    uint32_t kb[4];
                    ldsm4(kb, sK + kboff + (half * 64 + np * 16) * 272 + k8 * 32);
                    mma8(acc[2 * np],     qa[k8], kb,     acc[2 * np]);
                    mma8(acc[2 * np + 1], qa[k8], kb + 2, acc[2 * np + 1]);
                }
            // ---- rel-shift BD add, scale, online softmax ----
            int jb = it * 128 + half * 64;
            float mx0 = -1e30f, mx1 = -1e30f;
#pragma unroll
            for (int nt = 0; nt < 8; nt++) {
                int c0 = jb + nt * 8 + 2 * (l & 3);
                float s;
                s = (acc[nt][0] + bdval(bd, row0, c0))     * CS; acc[nt][0] = s; mx0 = fmaxf(mx0, s);
                s = (acc[nt][1] + bdval(bd, row0, c0 + 1)) * CS; acc[nt][1] = s; mx0 = fmaxf(mx0, s);
                s = (acc[nt][2] + bdval(bd, row1, c0))     * CS; acc[nt][2] = s; mx1 = fmaxf(mx1, s);
                s = (acc[nt][3] + bdval(bd, row1, c0 + 1)) * CS; acc[nt][3] = s; mx1 = fmaxf(mx1, s);
            }
            mx0 = fmaxf(mx0, __shfl_xor_sync(~0u, mx0, 1));
            mx0 = fmaxf(mx0, __shfl_xor_sync(~0u, mx0, 2));
            mx1 = fmaxf(mx1, __shfl_xor_sync(~0u, mx1, 1));
            mx1 = fmaxf(mx1, __shfl_xor_sync(~0u, mx1, 2));
            float mn0 = fmaxf(mrow0, mx0), mn1 = fmaxf(mrow1, mx1);
            float al0 = ex2(mrow0 - mn0), al1 = ex2(mrow1 - mn1);
            mrow0 = mn0; mrow1 = mn1;
            float rs0 = 0.f, rs1 = 0.f;
#pragma unroll
            for (int nt = 0; nt < 8; nt++) {
                float p0 = ex2(acc[nt][0] - mn0), p1 = ex2(acc[nt][1] - mn0);
                float p2 = ex2(acc[nt][2] - mn1), p3 = ex2(acc[nt][3] - mn1);
                rs0 += p0 + p1; rs1 += p2 + p3;
                int c = nt * 8 + 2 * (l & 3);
                *(float2*)&Ps[lr0 * 68 + c]       = make_float2(p0, p1);
                *(float2*)&Ps[(lr0 + 8) * 68 + c] = make_float2(p2, p3);
            }
            rs0 += __shfl_xor_sync(~0u, rs0, 1); rs0 += __shfl_xor_sync(~0u, rs0, 2);
            rs1 += __shfl_xor_sync(~0u, rs1, 1); rs1 += __shfl_xor_sync(~0u, rs1, 2);
            lsum0 = lsum0 * al0 + rs0;
            lsum1 = lsum1 * al1 + rs1;
#pragma unroll
            for (int nt = 0; nt < 8; nt++) {
                o[nt][0] *= al0; o[nt][1] *= al0; o[nt][2] *= al1; o[nt][3] *= al1;
            }
            if (half == 0) cpwait<0>();   // V(it) complete
            __syncthreads();              // Ps visible (+ Vs for half 0)

            if (half == 1 && it + 1 < 16) {   // Ks free (all warps past AC h1)
                const float* kn = Kg + (size_t)((it + 1) * 128) * ARS_;
#pragma unroll
                for (int t = 0; t < 8; t++) {
                    int idx = tid + t * 256; int r = idx >> 4, c4 = (idx & 15) << 2;
                    cpa16(sK + (r * 68 + c4) * 4, kn + (size_t)r * ARS_ + c4);
                }
                cpcommit();
            }

            // ---- PV: O += P . V (64 k-rows) ----
#pragma unroll
            for (int k8 = 0; k8 < 8; k8++) {
                uint32_t pa[4];
                ldsm4(pa, sQ + aoff + k8 * 32);
                int kr = half * 64 + k8 * 8 + (l & 3);
#pragma unroll
                for (int nt = 0; nt < 8; nt++) {
                    uint32_t vb[2];
                    vb[0] = f2u(Vs[kr * 72 + nt * 8 + (l >> 2)]);
                    vb[1] = f2u(Vs[(kr + 4) * 72 + nt * 8 + (l >> 2)]);
                    mma8(o[nt], pa, vb, o[nt]);
                }
            }
            __syncthreads();              // Ps reusable (h0) / Vs free (h1)

            if (half == 1 && it + 1 < 16) {
                const float* vn = Vg + (size_t)((it + 1) * 128) * ARS_;
#pragma unroll
                for (int t = 0; t < 8; t++) {
                    int idx = tid + t * 256; int r = idx >> 4, c4 = (idx & 15) << 2;
                    cpa16(sV + (r * 72 + c4) * 4, vn + (size_t)r * ARS_ + c4);
                }
                cpcommit();
            }
        }
    }

    float inv0 = 1.f / lsum0, inv1 = 1.f / lsum1;
#pragma unroll
    for (int nt = 0; nt < 8; nt++) {
        int c = h * 64 + nt * 8 + 2 * (l & 3);
        *(float2*)(g_att + ((size_t)row0 * B_ + b) * D_ + c) =
            make_float2(o[nt][0] * inv0, o[nt][1] * inv0);
        *(float2*)(g_att + ((size_t)row1 * B_ + b) * D_ + c) =
            make_float2(o[nt][2] * inv1, o[nt][3] * inv1);
    }
}

// ============================================================
// LayerNorm over D=1024 per row.
// ============================================================
__global__ __launch_bounds__(256) void ln_k(const float* __restrict__ gamma,
                                            const float* __restrict__ beta,
                                            float* __restrict__ out)
{
    __shared__ float reds[8], redq[8];
    const float* y = g_y + (size_t)blockIdx.x * D_;
    int tid = threadIdx.x;
    float v[4];
    float s = 0.f, q = 0.f;
#pragma unroll
    for (int t = 0; t < 4; t++) {
        v[t] = y[tid + t * 256];
        s += v[t]; q += v[t] * v[t];
    }
#pragma unroll
    for (int o = 16; o; o >>= 1) {
        s += __shfl_xor_sync(0xffffffffu, s, o);
        q += __shfl_xor_sync(0xffffffffu, q, o);
    }
    if ((tid & 31) == 0) { reds[tid >> 5] = s; redq[tid >> 5] = q; }
    __syncthreads();
    float ts = 0.f, tq = 0.f;
#pragma unroll
    for (int wv = 0; wv < 8; wv++) { ts += reds[wv]; tq += redq[wv]; }
    float mu = ts * (1.f / 1024.f);
    float var = tq * (1.f / 1024.f) - mu * mu;
    float inv = rsqrtf(var + 1e-5f);
    float* op = out + (size_t)blockIdx.x * D_;
#pragma unroll
    for (int t = 0; t < 4; t++) {
        int c = tid + t * 256;
        op[c] = (v[t] - mu) * inv * gamma[c] + beta[c];
    }
}

// ============================================================
extern "C" void kernel_launch(void* const* d_in, const int* in_sizes, int n_in,
                              void* d_out, int out_size)
{
    const float* x    = (const float*)d_in[0];
    const float* pe   = (const float*)d_in[1];
    const float* pbu  = (const float*)d_in[2];
    const float* pbv  = (const float*)d_in[3];
    const float* Wqkv = (const float*)d_in[4];
    const float* Wrel = (const float*)d_in[5];
    const float* Wo   = (const float*)d_in[6];
    const float* gam  = (const float*)d_in[7];
    const float* bet  = (const float*)d_in[8];
    float* out = (float*)d_out;

    const int PG_SMEM = 71680;     // (9216 + 8704) * 4
    const int BD_SMEM = 69632;     // 2 * 128*68 * 4
    const int FA_SMEM = 106496;    // (8704 + 8704 + 9216) * 4
    cudaFuncSetAttribute(pgemm<0>, cudaFuncAttributeMaxDynamicSharedMemorySize, PG_SMEM);
    cudaFuncSetAttribute(pgemm<1>, cudaFuncAttributeMaxDynamicSharedMemorySize, PG_SMEM);
    cudaFuncSetAttribute(pgemm<2>, cudaFuncAttributeMaxDynamicSharedMemorySize, PG_SMEM);
    cudaFuncSetAttribute(bd_gemm,  cudaFuncAttributeMaxDynamicSharedMemorySize, BD_SMEM);
    cudaFuncSetAttribute(fattn,    cudaFuncAttributeMaxDynamicSharedMemorySize, FA_SMEM);

    // 1) qkv = x @ W_qkv
    pgemm<0><<<dim3(24, 32), 256, PG_SMEM>>>(x, Wqkv, nullptr, 3072);
    // 2) r = pos_emb @ W_relemb
    pgemm<1><<<dim3(8, 16), 256, PG_SMEM>>>(pe, Wrel, nullptr, 1024);
    // 3) Draw = (q + pbv) @ r^T per (b,h)
    bd_gemm<<<dim3(16, 16, 32), 256, BD_SMEM>>>(pbv);
    // 4) fused: scores + rel-shift + softmax + PV
    fattn<<<dim3(16, 32), 256, FA_SMEM>>>(pbu);
    // 5) y = x + attn_vec @ W_o
    pgemm<2><<<dim3(8, 32), 256, PG_SMEM>>>(nullptr, Wo, x, 1024);
    // 6) layernorm
    ln_k<<<4096, 256>>>(gam, bet, out);
}

// round 5
// speedup vs baseline: 2.8580x; 1.0191x over previous
#include <cuda_runtime.h>
#include <stdint.h>

#define S_    2048
#define B_    2
#define D_    1024
#define H_    16
#define BH_   32
#define ROWS_ 4096
#define QLD_  3072
#define ARS_  6144   // B_*QLD_ : stride between seq rows in g_qkv

// ---- scratch (static device globals; no allocation) ----
__device__ float g_qkv[(size_t)ROWS_ * 3072];          // [s*B+b][q|k|v]
__device__ float g_r  [(size_t)S_ * D_];               // [t][h*64+d]
__device__ float g_bd [(size_t)BH_ * S_ * S_];         // Draw per (b,h)
__device__ float g_att[(size_t)ROWS_ * D_];            // attn_vec
__device__ float g_y  [(size_t)ROWS_ * D_];            // x + attn_out

// ---------------- mma / cp.async / ldmatrix helpers ----------------
__device__ __forceinline__ void mma8(float* d, const uint32_t* a,
                                     const uint32_t* b, const float* c) {
    asm volatile(
        "mma.sync.aligned.m16n8k8.row.col.f32.tf32.tf32.f32 "
        "{%0,%1,%2,%3}, {%4,%5,%6,%7}, {%8,%9}, {%10,%11,%12,%13};\n"
        : "=f"(d[0]), "=f"(d[1]), "=f"(d[2]), "=f"(d[3])
        : "r"(a[0]), "r"(a[1]), "r"(a[2]), "r"(a[3]), "r"(b[0]), "r"(b[1]),
          "f"(c[0]), "f"(c[1]), "f"(c[2]), "f"(c[3]));
}
__device__ __forceinline__ uint32_t f2u(float x) { return __float_as_uint(x); }
__device__ __forceinline__ void cpa16(uint32_t s, const void* g) {
    asm volatile("cp.async.cg.shared.global [%0], [%1], 16;\n" :: "r"(s), "l"(g));
}
__device__ __forceinline__ void cpcommit() { asm volatile("cp.async.commit_group;\n"); }
template <int N> __device__ __forceinline__ void cpwait() {
    asm volatile("cp.async.wait_group %0;\n" :: "n"(N));
}
__device__ __forceinline__ void ldsm4(uint32_t* r, uint32_t a) {
    asm volatile("ldmatrix.sync.aligned.m8n8.x4.shared.b16 {%0,%1,%2,%3}, [%4];\n"
        : "=r"(r[0]), "=r"(r[1]), "=r"(r[2]), "=r"(r[3]) : "r"(a));
}
__device__ __forceinline__ float ex2(float x) {
    float y; asm("ex2.approx.f32 %0, %1;" : "=f"(y) : "f"(x)); return y;
}

// ============================================================
// Projection GEMM, K=1024 fixed, tile 128x128x32, cp.async 2-stage.
// MODE 0: g_qkv = A@B   1: g_r = A@B   2: g_y = g_att@B + Xres
// ============================================================
template <int MODE>
__global__ __launch_bounds__(256) void pgemm(const float* __restrict__ A,
                                             const float* __restrict__ Bw,
                                             const float* __restrict__ Xres,
                                             int N)
{
    extern __shared__ float sm[];
    float* As = sm;               // 2 x 128 x 36
    float* Bs = sm + 9216;        // 2 x 32  x 136
    const float* Ap = (MODE == 2) ? (const float*)g_att : A;
    float* C = (MODE == 0) ? g_qkv : (MODE == 1) ? g_r : g_y;

    int tid = threadIdx.x, l = tid & 31, w = tid >> 5, wm = w >> 1, wn = w & 1;
    size_t m0 = (size_t)blockIdx.y * 128, n0 = (size_t)blockIdx.x * 128;
    uint32_t sA = (uint32_t)__cvta_generic_to_shared(As);
    uint32_t sB = (uint32_t)__cvta_generic_to_shared(Bs);

    float acc[2][8][4] = {};

#define STAGE(IT, BUF)                                                          \
    {                                                                           \
        int kk = (IT) * 32;                                                     \
        uint32_t ab = sA + (BUF) * 4608 * 4;                                    \
        _Pragma("unroll")                                                       \
        for (int t = 0; t < 4; t++) {                                           \
            int idx = tid + t * 256; int r = idx >> 3, c4 = (idx & 7) << 2;     \
            cpa16(ab + (r * 36 + c4) * 4, Ap + (m0 + r) * 1024 + kk + c4);      \
        }                                                                       \
        uint32_t bb = sB + (BUF) * 4352 * 4;                                    \
        _Pragma("unroll")                                                       \
        for (int t = 0; t < 4; t++) {                                           \
            int idx = tid + t * 256; int r = idx >> 5, c4 = (idx & 31) << 2;    \
            cpa16(bb + (r * 136 + c4) * 4, Bw + (size_t)(kk + r) * N + n0 + c4);\
        }                                                                       \
        cpcommit();                                                             \
    }

    STAGE(0, 0);
    for (int it = 0; it < 32; it++) {
        int buf = it & 1;
        if (it + 1 < 32) { STAGE(it + 1, buf ^ 1); cpwait<1>(); }
        else             { cpwait<0>(); }
        __syncthreads();
        const float* As_ = As + buf * 4608;
        const float* Bs_ = Bs + buf * 4352;
#pragma unroll
        for (int k8 = 0; k8 < 4; k8++) {
            uint32_t a[2][4];
#pragma unroll
            for (int mt = 0; mt < 2; mt++) {
                int r = wm * 32 + mt * 16 + (l >> 2);
                a[mt][0] = f2u(As_[r * 36 + k8 * 8 + (l & 3)]);
                a[mt][1] = f2u(As_[(r + 8) * 36 + k8 * 8 + (l & 3)]);
                a[mt][2] = f2u(As_[r * 36 + k8 * 8 + (l & 3) + 4]);
                a[mt][3] = f2u(As_[(r + 8) * 36 + k8 * 8 + (l & 3) + 4]);
            }
#pragma unroll
            for (int nt = 0; nt < 8; nt++) {
                uint32_t bf[2];
                int cb = wn * 64 + nt * 8 + (l >> 2);
                bf[0] = f2u(Bs_[(k8 * 8 + (l & 3)) * 136 + cb]);
                bf[1] = f2u(Bs_[(k8 * 8 + (l & 3) + 4) * 136 + cb]);
#pragma unroll
                for (int mt = 0; mt < 2; mt++)
                    mma8(acc[mt][nt], a[mt], bf, acc[mt][nt]);
            }
        }
        __syncthreads();
    }
#undef STAGE

#pragma unroll
    for (int mt = 0; mt < 2; mt++) {
        size_t r0 = m0 + wm * 32 + mt * 16 + (l >> 2);
#pragma unroll
        for (int nt = 0; nt < 8; nt++) {
            size_t c = n0 + wn * 64 + nt * 8 + 2 * (l & 3);
            float2 v0 = make_float2(acc[mt][nt][0], acc[mt][nt][1]);
            float2 v1 = make_float2(acc[mt][nt][2], acc[mt][nt][3]);
            if (MODE == 2) {
                float2 x0 = *(const float2*)(Xres + r0 * N + c);
                float2 x1 = *(const float2*)(Xres + (r0 + 8) * N + c);
                v0.x += x0.x; v0.y += x0.y; v1.x += x1.x; v1.y += x1.y;
            }
            *(float2*)(C + r0 * N + c) = v0;
            *(float2*)(C + (r0 + 8) * N + c) = v1;
        }
    }
}

// ============================================================
// Draw = (q + pos_bias_v) @ r^T per (b,h). 128x128, K=64, ldmatrix.
// ============================================================
__global__ __launch_bounds__(256, 2) void bd_gemm(const float* __restrict__ pbv)
{
    extern __shared__ float sm[];
    float* Qs = sm;               // 128 x 68
    float* Rs = sm + 8704;        // 128 x 68
    int tid = threadIdx.x, l = tid & 31, w = tid >> 5;
    int bh = blockIdx.z, b = bh >> 4, h = bh & 15;
    int i0 = blockIdx.y * 128, t0 = blockIdx.x * 128;
    const float* Qg = g_qkv + (size_t)b * QLD_ + h * 64;
    const float* Rg = g_r + h * 64;
    const float* bias = pbv + h * 64;

#pragma unroll
    for (int t = 0; t < 8; t++) {
        int idx = tid + t * 256; int r = idx >> 4, c4 = (idx & 15) << 2;
        float4 a4 = *(const float4*)(Qg + (size_t)(i0 + r) * ARS_ + c4);
        float4 u4 = *(const float4*)(bias + c4);
        a4.x += u4.x; a4.y += u4.y; a4.z += u4.z; a4.w += u4.w;
        *(float4*)&Qs[r * 68 + c4] = a4;
        *(float4*)&Rs[r * 68 + c4] = *(const float4*)(Rg + (size_t)(t0 + r) * D_ + c4);
    }
    __syncthreads();

    uint32_t sQ = (uint32_t)__cvta_generic_to_shared(Qs);
    uint32_t sR = (uint32_t)__cvta_generic_to_shared(Rs);
    uint32_t aoff = ((w * 16 + ((l >> 3) & 1) * 8 + (l & 7)) * 68 + ((l >> 4) & 1) * 4) * 4;
    uint32_t boff = ((((l >> 4) & 1) * 8 + (l & 7)) * 68 + ((l >> 3) & 1) * 4) * 4;

    uint32_t qa[8][4];
#pragma unroll
    for (int k8 = 0; k8 < 8; k8++) ldsm4(qa[k8], sQ + aoff + k8 * 32);

    float acc[16][4] = {};
#pragma unroll
    for (int k8 = 0; k8 < 8; k8++)
#pragma unroll
        for (int np = 0; np < 8; np++) {
            uint32_t kb[4];
            ldsm4(kb, sR + boff + np * 16 * 272 + k8 * 32);
            mma8(acc[2 * np],     qa[k8], kb,     acc[2 * np]);
            mma8(acc[2 * np + 1], qa[k8], kb + 2, acc[2 * np + 1]);
        }

    float* out = g_bd + (size_t)bh * S_ * S_;
    int gr = i0 + w * 16 + (l >> 2);
#pragma unroll
    for (int nt = 0; nt < 16; nt++) {
        int gc = t0 + nt * 8 + 2 * (l & 3);
        *(float2*)(out + (size_t)gr * S_ + gc)       = make_float2(acc[nt][0], acc[nt][1]);
        *(float2*)(out + (size_t)(gr + 8) * S_ + gc) = make_float2(acc[nt][2], acc[nt][3]);
    }
}

// ============================================================
// Fused attention: AC GEMM + rel-shift BD + online softmax + PV.
// 64-col halves; P kept in registers (quad shuffle-transpose);
// no P smem staging; 2 CTAs/SM; ~85 live regs (no spills).
// ============================================================
__device__ __forceinline__ float bdval(const float* bd, int i, int j)
{
    if (j <= i)      return __ldg(bd + (size_t)i * S_ + (S_ - 1 + j - i));
    if (j == i + 1)  return 0.f;
    return __ldg(bd + (size_t)(i + 1) * S_ + (j - i - 2));
}

__global__ __launch_bounds__(256, 2) void fattn(const float* __restrict__ pbu)
{
    extern __shared__ float sm[];
    float* Qs = sm;                    // 128 x 68 (persistent)
    float* Ks = sm + 8704;             // 128 x 68
    float* Vs = sm + 17408;            // 128 x 72
    int tid = threadIdx.x, l = tid & 31, w = tid >> 5;
    int bh = blockIdx.y, b = bh >> 4, h = bh & 15;
    int i0 = blockIdx.x * 128;
    const float* Qg = g_qkv + (size_t)b * QLD_ + h * 64;
    const float* Kg = Qg + 1024;
    const float* Vg = Qg + 2048;
    const float* bd = g_bd + (size_t)bh * S_ * S_;
    const float* bias = pbu + h * 64;
    uint32_t sQ = (uint32_t)__cvta_generic_to_shared(Qs);
    uint32_t sK = (uint32_t)__cvta_generic_to_shared(Ks);
    uint32_t sV = (uint32_t)__cvta_generic_to_shared(Vs);

    // Q + bias_u -> smem; prefetch K0, V0 as separate cp.async groups
#pragma unroll
    for (int t = 0; t < 8; t++) {
        int idx = tid + t * 256; int r = idx >> 4, c4 = (idx & 15) << 2;
        float4 a4 = *(const float4*)(Qg + (size_t)(i0 + r) * ARS_ + c4);
        float4 u4 = *(const float4*)(bias + c4);
        a4.x += u4.x; a4.y += u4.y; a4.z += u4.z; a4.w += u4.w;
        *(float4*)&Qs[r * 68 + c4] = a4;
    }
#pragma unroll
    for (int t = 0; t < 8; t++) {
        int idx = tid + t * 256; int r = idx >> 4, c4 = (idx & 15) << 2;
        cpa16(sK + (r * 68 + c4) * 4, Kg + (size_t)r * ARS_ + c4);
    }
    cpcommit();
#pragma unroll
    for (int t = 0; t < 8; t++) {
        int idx = tid + t * 256; int r = idx >> 4, c4 = (idx & 15) << 2;
        cpa16(sV + (r * 72 + c4) * 4, Vg + (size_t)r * ARS_ + c4);
    }
    cpcommit();

    uint32_t aoff = ((w * 16 + ((l >> 3) & 1) * 8 + (l & 7)) * 68 + ((l >> 4) & 1) * 4) * 4;
    uint32_t kboff = ((((l >> 4) & 1) * 8 + (l & 7)) * 68 + ((l >> 3) & 1) * 4) * 4;

    float o[8][4] = {};
    float mrow0 = -1e30f, mrow1 = -1e30f, lsum0 = 0.f, lsum1 = 0.f;
    int tc = l & 3;
    int lr0 = w * 16 + (l >> 2);
    int row0 = i0 + lr0, row1 = row0 + 8;
    int srcq = (l & ~3) | (tc >> 1);
    bool oddc = tc & 1;
    const float CS = 0.1803368801111204f;   // 0.125 * log2(e)
    __syncthreads();   // Qs visible to ldmatrix (warps write others' rows)

#define HALF_STEP(HALF, JB)                                                     \
    {                                                                           \
        float p[8][4];                                                          \
        _Pragma("unroll")                                                       \
        for (int nt = 0; nt < 8; nt++)                                          \
            p[nt][0] = p[nt][1] = p[nt][2] = p[nt][3] = 0.f;                    \
        _Pragma("unroll")                                                       \
        for (int k8 = 0; k8 < 8; k8++) {                                        \
            uint32_t qf[4];                                                     \
            ldsm4(qf, sQ + aoff + k8 * 32);                                     \
            _Pragma("unroll")                                                   \
            for (int np = 0; np < 4; np++) {                                    \
                uint32_t kb[4];                                                 \
                ldsm4(kb, sK + kboff + ((HALF) * 64 + np * 16) * 272 + k8 * 32);\
                mma8(p[2 * np],     qf, kb,     p[2 * np]);                     \
                mma8(p[2 * np + 1], qf, kb + 2, p[2 * np + 1]);                 \
            }                                                                   \
        }                                                                       \
        float mx0 = -1e30f, mx1 = -1e30f;                                       \
        _Pragma("unroll")                                                       \
        for (int nt = 0; nt < 8; nt++) {                                        \
            int c0 = (JB) + nt * 8 + 2 * tc;                                    \
            float s;                                                            \
            s = (p[nt][0] + bdval(bd, row0, c0))     * CS; p[nt][0] = s; mx0 = fmaxf(mx0, s); \
            s = (p[nt][1] + bdval(bd, row0, c0 + 1)) * CS; p[nt][1] = s; mx0 = fmaxf(mx0, s); \
            s = (p[nt][2] + bdval(bd, row1, c0))     * CS; p[nt][2] = s; mx1 = fmaxf(mx1, s); \
            s = (p[nt][3] + bdval(bd, row1, c0 + 1)) * CS; p[nt][3] = s; mx1 = fmaxf(mx1, s); \
        }                                                                       \
        mx0 = fmaxf(mx0, __shfl_xor_sync(~0u, mx0, 1));                         \
        mx0 = fmaxf(mx0, __shfl_xor_sync(~0u, mx0, 2));                         \
        mx1 = fmaxf(mx1, __shfl_xor_sync(~0u, mx1, 1));                         \
        mx1 = fmaxf(mx1, __shfl_xor_sync(~0u, mx1, 2));                         \
        float mn0 = fmaxf(mrow0, mx0), mn1 = fmaxf(mrow1, mx1);                 \
        float al0 = ex2(mrow0 - mn0), al1 = ex2(mrow1 - mn1);                   \
        mrow0 = mn0; mrow1 = mn1;                                               \
        float rs0 = 0.f, rs1 = 0.f;                                             \
        _Pragma("unroll")                                                       \
        for (int nt = 0; nt < 8; nt++) {                                        \
            p[nt][0] = ex2(p[nt][0] - mn0); p[nt][1] = ex2(p[nt][1] - mn0);     \
            p[nt][2] = ex2(p[nt][2] - mn1); p[nt][3] = ex2(p[nt][3] - mn1);     \
            rs0 += p[nt][0] + p[nt][1]; rs1 += p[nt][2] + p[nt][3];             \
        }                                                                       \
        rs0 += __shfl_xor_sync(~0u, rs0, 1); rs0 += __shfl_xor_sync(~0u, rs0, 2);\
        rs1 += __shfl_xor_sync(~0u, rs1, 1); rs1 += __shfl_xor_sync(~0u, rs1, 2);\
        lsum0 = lsum0 * al0 + rs0;                                              \
        lsum1 = lsum1 * al1 + rs1;                                              \
        _Pragma("unroll")                                                       \
        for (int nt = 0; nt < 8; nt++) {                                        \
            o[nt][0] *= al0; o[nt][1] *= al0; o[nt][2] *= al1; o[nt][3] *= al1; \
        }                                                                       \
        PV_SYNC(HALF)                                                           \
        _Pragma("unroll")                                                       \
        for (int k8 = 0; k8 < 8; k8++) {                                        \
            float e00 = __shfl_sync(~0u, p[k8][0], srcq);                       \
            float e01 = __shfl_sync(~0u, p[k8][1], srcq);                       \
            float e10 = __shfl_sync(~0u, p[k8][0], srcq + 2);                   \
            float e11 = __shfl_sync(~0u, p[k8][1], srcq + 2);                   \
            float f00 = __shfl_sync(~0u, p[k8][2], srcq);                       \
            float f01 = __shfl_sync(~0u, p[k8][3], srcq);                       \
            float f10 = __shfl_sync(~0u, p[k8][2], srcq + 2);                   \
            float f11 = __shfl_sync(~0u, p[k8][3], srcq + 2);                   \
            uint32_t af[4];                                                     \
            af[0] = f2u(oddc ? e01 : e00);                                      \
            af[1] = f2u(oddc ? f01 : f00);                                      \
            af[2] = f2u(oddc ? e11 : e10);                                      \
            af[3] = f2u(oddc ? f11 : f10);                                      \
            int kr = (HALF) * 64 + k8 * 8 + tc;                                 \
            _Pragma("unroll")                                                   \
            for (int nt = 0; nt < 8; nt++) {                                    \
                uint32_t vb[2];                                                 \
                vb[0] = f2u(Vs[kr * 72 + nt * 8 + (l >> 2)]);                   \
                vb[1] = f2u(Vs[(kr + 4) * 72 + nt * 8 + (l >> 2)]);             \
                mma8(o[nt], af, vb, o[nt]);                                     \
            }                                                                   \
        }                                                                       \
    }

    for (int it = 0; it < 16; it++) {
        cpwait<1>();          // K(it) landed (this thread); V(it) may be pending
        __syncthreads();      // all threads' K(it) done -> Ks readable

#define PV_SYNC(HALF) { cpwait<0>(); __syncthreads(); }
        HALF_STEP(0, it * 128)
#undef PV_SYNC
        // half 1: Ks reads finish in AC above; after barrier, refill Ks.
#define PV_SYNC(HALF)                                                           \
        {                                                                       \
            __syncthreads();  /* all warps done with Ks (AC h1) */              \
            if (it + 1 < 16) {                                                  \
                const float* kn = Kg + (size_t)((it + 1) * 128) * ARS_;         \
                _Pragma("unroll")                                               \
                for (int t = 0; t < 8; t++) {                                   \
                    int idx = tid + t * 256;                                    \
                    int r = idx >> 4, c4 = (idx & 15) << 2;                     \
                    cpa16(sK + (r * 68 + c4) * 4, kn + (size_t)r * ARS_ + c4);  \
                }                                                               \
                cpcommit();                                                     \
            }                                                                   \
        }
        HALF_STEP(1, it * 128 + 64)
#undef PV_SYNC

        __syncthreads();      // all warps done reading Vs (PV h1)
        if (it + 1 < 16) {
            const float* vn = Vg + (size_t)((it + 1) * 128) * ARS_;
#pragma unroll
            for (int t = 0; t < 8; t++) {
                int idx = tid + t * 256; int r = idx >> 4, c4 = (idx & 15) << 2;
                cpa16(sV + (r * 72 + c4) * 4, vn + (size_t)r * ARS_ + c4);
            }
            cpcommit();
        }
    }
#undef HALF_STEP

    float inv0 = 1.f / lsum0, inv1 = 1.f / lsum1;
#pragma unroll
    for (int nt = 0; nt < 8; nt++) {
        int c = h * 64 + nt * 8 + 2 * tc;
        *(float2*)(g_att + ((size_t)row0 * B_ + b) * D_ + c) =
            make_float2(o[nt][0] * inv0, o[nt][1] * inv0);
        *(float2*)(g_att + ((size_t)row1 * B_ + b) * D_ + c) =
            make_float2(o[nt][2] * inv1, o[nt][3] * inv1);
    }
}

// ============================================================
// LayerNorm over D=1024 per row.
// ============================================================
__global__ __launch_bounds__(256) void ln_k(const float* __restrict__ gamma,
                                            const float* __restrict__ beta,
                                            float* __restrict__ out)
{
    __shared__ float reds[8], redq[8];
    const float* y = g_y + (size_t)blockIdx.x * D_;
    int tid = threadIdx.x;
    float v[4];
    float s = 0.f, q = 0.f;
#pragma unroll
    for (int t = 0; t < 4; t++) {
        v[t] = y[tid + t * 256];
        s += v[t]; q += v[t] * v[t];
    }
#pragma unroll
    for (int o = 16; o; o >>= 1) {
        s += __shfl_xor_sync(0xffffffffu, s, o);
        q += __shfl_xor_sync(0xffffffffu, q, o);
    }
    if ((tid & 31) == 0) { reds[tid >> 5] = s; redq[tid >> 5] = q; }
    __syncthreads();
    float ts = 0.f, tq = 0.f;
#pragma unroll
    for (int wv = 0; wv < 8; wv++) { ts += reds[wv]; tq += redq[wv]; }
    float mu = ts * (1.f / 1024.f);
    float var = tq * (1.f / 1024.f) - mu * mu;
    float inv = rsqrtf(var + 1e-5f);
    float* op = out + (size_t)blockIdx.x * D_;
#pragma unroll
    for (int t = 0; t < 4; t++) {
        int c = tid + t * 256;
        op[c] = (v[t] - mu) * inv * gamma[c] + beta[c];
    }
}

// ============================================================
extern "C" void kernel_launch(void* const* d_in, const int* in_sizes, int n_in,
                              void* d_out, int out_size)
{
    const float* x    = (const float*)d_in[0];
    const float* pe   = (const float*)d_in[1];
    const float* pbu  = (const float*)d_in[2];
    const float* pbv  = (const float*)d_in[3];
    const float* Wqkv = (const float*)d_in[4];
    const float* Wrel = (const float*)d_in[5];
    const float* Wo   = (const float*)d_in[6];
    const float* gam  = (const float*)d_in[7];
    const float* bet  = (const float*)d_in[8];
    float* out = (float*)d_out;

    const int PG_SMEM = 71680;     // (9216 + 8704) * 4
    const int BD_SMEM = 69632;     // 2 * 128*68 * 4
    const int FA_SMEM = 106496;    // (8704 + 8704 + 9216) * 4
    cudaFuncSetAttribute(pgemm<0>, cudaFuncAttributeMaxDynamicSharedMemorySize, PG_SMEM);
    cudaFuncSetAttribute(pgemm<1>, cudaFuncAttributeMaxDynamicSharedMemorySize, PG_SMEM);
    cudaFuncSetAttribute(pgemm<2>, cudaFuncAttributeMaxDynamicSharedMemorySize, PG_SMEM);
    cudaFuncSetAttribute(bd_gemm,  cudaFuncAttributeMaxDynamicSharedMemorySize, BD_SMEM);
    cudaFuncSetAttribute(fattn,    cudaFuncAttributeMaxDynamicSharedMemorySize, FA_SMEM);

    // 1) qkv = x @ W_qkv
    pgemm<0><<<dim3(24, 32), 256, PG_SMEM>>>(x, Wqkv, nullptr, 3072);
    // 2) r = pos_emb @ W_relemb
    pgemm<1><<<dim3(8, 16), 256, PG_SMEM>>>(pe, Wrel, nullptr, 1024);
    // 3) Draw = (q + pbv) @ r^T per (b,h)
    bd_gemm<<<dim3(16, 16, 32), 256, BD_SMEM>>>(pbv);
    // 4) fused: scores + rel-shift + softmax + PV
    fattn<<<dim3(16, 32), 256, FA_SMEM>>>(pbu);
    // 5) y = x + attn_vec @ W_o
    pgemm<2><<<dim3(8, 32), 256, PG_SMEM>>>(nullptr, Wo, x, 1024);
    // 6) layernorm
    ln_k<<<4096, 256>>>(gam, bet, out);
}

// round 6
// speedup vs baseline: 3.1500x; 1.1022x over previous
#include <cuda_runtime.h>
#include <stdint.h>

#define S_    2048
#define B_    2
#define D_    1024
#define H_    16
#define BH_   32
#define ROWS_ 4096
#define QLD_  3072
#define ARS_  6144   // B_*QLD_ : stride between seq rows in g_qkv

// ---- scratch (static device globals; no allocation) ----
__device__ float g_qkv[(size_t)ROWS_ * 3072];          // [s*B+b][q|k|v]
__device__ float g_r  [(size_t)S_ * D_];               // [t][h*64+d]
__device__ float g_bd [(size_t)BH_ * S_ * S_];         // Draw per (b,h)
__device__ float g_att[(size_t)ROWS_ * D_];            // attn_vec
__device__ float g_y  [(size_t)ROWS_ * D_];            // x + attn_out

// ---------------- mma / cp.async / ldmatrix helpers ----------------
__device__ __forceinline__ void mma8(float* d, const uint32_t* a,
                                     const uint32_t* b, const float* c) {
    asm volatile(
        "mma.sync.aligned.m16n8k8.row.col.f32.tf32.tf32.f32 "
        "{%0,%1,%2,%3}, {%4,%5,%6,%7}, {%8,%9}, {%10,%11,%12,%13};\n"
        : "=f"(d[0]), "=f"(d[1]), "=f"(d[2]), "=f"(d[3])
        : "r"(a[0]), "r"(a[1]), "r"(a[2]), "r"(a[3]), "r"(b[0]), "r"(b[1]),
          "f"(c[0]), "f"(c[1]), "f"(c[2]), "f"(c[3]));
}
__device__ __forceinline__ uint32_t f2u(float x) { return __float_as_uint(x); }
__device__ __forceinline__ void cpa16(uint32_t s, const void* g) {
    asm volatile("cp.async.cg.shared.global [%0], [%1], 16;\n" :: "r"(s), "l"(g));
}
__device__ __forceinline__ void cpcommit() { asm volatile("cp.async.commit_group;\n"); }
template <int N> __device__ __forceinline__ void cpwait() {
    asm volatile("cp.async.wait_group %0;\n" :: "n"(N));
}
__device__ __forceinline__ void ldsm4(uint32_t* r, uint32_t a) {
    asm volatile("ldmatrix.sync.aligned.m8n8.x4.shared.b16 {%0,%1,%2,%3}, [%4];\n"
        : "=r"(r[0]), "=r"(r[1]), "=r"(r[2]), "=r"(r[3]) : "r"(a));
}
__device__ __forceinline__ float ex2(float x) {
    float y; asm("ex2.approx.f32 %0, %1;" : "=f"(y) : "f"(x)); return y;
}

// ============================================================
// Projection GEMM, K=1024 fixed, tile 128x128x32, cp.async 2-stage.
// MODE 0: g_qkv = A@B   1: g_r = A@B   2: g_y = g_att@B + Xres
// ============================================================
template <int MODE>
__global__ __launch_bounds__(256) void pgemm(const float* __restrict__ A,
                                             const float* __restrict__ Bw,
                                             const float* __restrict__ Xres,
                                             int N)
{
    extern __shared__ float sm[];
    float* As = sm;               // 2 x 128 x 36
    float* Bs = sm + 9216;        // 2 x 32  x 136
    const float* Ap = (MODE == 2) ? (const float*)g_att : A;
    float* C = (MODE == 0) ? g_qkv : (MODE == 1) ? g_r : g_y;

    int tid = threadIdx.x, l = tid & 31, w = tid >> 5, wm = w >> 1, wn = w & 1;
    size_t m0 = (size_t)blockIdx.y * 128, n0 = (size_t)blockIdx.x * 128;
    uint32_t sA = (uint32_t)__cvta_generic_to_shared(As);
    uint32_t sB = (uint32_t)__cvta_generic_to_shared(Bs);

    float acc[2][8][4] = {};

#define STAGE(IT, BUF)                                                          \
    {                                                                           \
        int kk = (IT) * 32;                                                     \
        uint32_t ab = sA + (BUF) * 4608 * 4;                                    \
        _Pragma("unroll")                                                       \
        for (int t = 0; t < 4; t++) {                                           \
            int idx = tid + t * 256; int r = idx >> 3, c4 = (idx & 7) << 2;     \
            cpa16(ab + (r * 36 + c4) * 4, Ap + (m0 + r) * 1024 + kk + c4);      \
        }                                                                       \
        uint32_t bb = sB + (BUF) * 4352 * 4;                                    \
        _Pragma("unroll")                                                       \
        for (int t = 0; t < 4; t++) {                                           \
            int idx = tid + t * 256; int r = idx >> 5, c4 = (idx & 31) << 2;    \
            cpa16(bb + (r * 136 + c4) * 4, Bw + (size_t)(kk + r) * N + n0 + c4);\
        }                                                                       \
        cpcommit();                                                             \
    }

    STAGE(0, 0);
    for (int it = 0; it < 32; it++) {
        int buf = it & 1;
        if (it + 1 < 32) { STAGE(it + 1, buf ^ 1); cpwait<1>(); }
        else             { cpwait<0>(); }
        __syncthreads();
        const float* As_ = As + buf * 4608;
        const float* Bs_ = Bs + buf * 4352;
#pragma unroll
        for (int k8 = 0; k8 < 4; k8++) {
            uint32_t a[2][4];
#pragma unroll
            for (int mt = 0; mt < 2; mt++) {
                int r = wm * 32 + mt * 16 + (l >> 2);
                a[mt][0] = f2u(As_[r * 36 + k8 * 8 + (l & 3)]);
                a[mt][1] = f2u(As_[(r + 8) * 36 + k8 * 8 + (l & 3)]);
                a[mt][2] = f2u(As_[r * 36 + k8 * 8 + (l & 3) + 4]);
                a[mt][3] = f2u(As_[(r + 8) * 36 + k8 * 8 + (l & 3) + 4]);
            }
#pragma unroll
            for (int nt = 0; nt < 8; nt++) {
                uint32_t bf[2];
                int cb = wn * 64 + nt * 8 + (l >> 2);
                bf[0] = f2u(Bs_[(k8 * 8 + (l & 3)) * 136 + cb]);
                bf[1] = f2u(Bs_[(k8 * 8 + (l & 3) + 4) * 136 + cb]);
#pragma unroll
                for (int mt = 0; mt < 2; mt++)
                    mma8(acc[mt][nt], a[mt], bf, acc[mt][nt]);
            }
        }
        __syncthreads();
    }
#undef STAGE

#pragma unroll
    for (int mt = 0; mt < 2; mt++) {
        size_t r0 = m0 + wm * 32 + mt * 16 + (l >> 2);
#pragma unroll
        for (int nt = 0; nt < 8; nt++) {
            size_t c = n0 + wn * 64 + nt * 8 + 2 * (l & 3);
            float2 v0 = make_float2(acc[mt][nt][0], acc[mt][nt][1]);
            float2 v1 = make_float2(acc[mt][nt][2], acc[mt][nt][3]);
            if (MODE == 2) {
                float2 x0 = *(const float2*)(Xres + r0 * N + c);
                float2 x1 = *(const float2*)(Xres + (r0 + 8) * N + c);
                v0.x += x0.x; v0.y += x0.y; v1.x += x1.x; v1.y += x1.y;
            }
            *(float2*)(C + r0 * N + c) = v0;
            *(float2*)(C + (r0 + 8) * N + c) = v1;
        }
    }
}

// ============================================================
// Draw = (q + pos_bias_v) @ r^T per (b,h). 128x128, K=64, ldmatrix.
// Streaming stores (written once, read once later).
// ============================================================
__global__ __launch_bounds__(256, 2) void bd_gemm(const float* __restrict__ pbv)
{
    extern __shared__ float sm[];
    float* Qs = sm;               // 128 x 68
    float* Rs = sm + 8704;        // 128 x 68
    int tid = threadIdx.x, l = tid & 31, w = tid >> 5;
    int bh = blockIdx.z, b = bh >> 4, h = bh & 15;
    int i0 = blockIdx.y * 128, t0 = blockIdx.x * 128;
    const float* Qg = g_qkv + (size_t)b * QLD_ + h * 64;
    const float* Rg = g_r + h * 64;
    const float* bias = pbv + h * 64;

#pragma unroll
    for (int t = 0; t < 8; t++) {
        int idx = tid + t * 256; int r = idx >> 4, c4 = (idx & 15) << 2;
        float4 a4 = *(const float4*)(Qg + (size_t)(i0 + r) * ARS_ + c4);
        float4 u4 = *(const float4*)(bias + c4);
        a4.x += u4.x; a4.y += u4.y; a4.z += u4.z; a4.w += u4.w;
        *(float4*)&Qs[r * 68 + c4] = a4;
        *(float4*)&Rs[r * 68 + c4] = *(const float4*)(Rg + (size_t)(t0 + r) * D_ + c4);
    }
    __syncthreads();

    uint32_t sQ = (uint32_t)__cvta_generic_to_shared(Qs);
    uint32_t sR = (uint32_t)__cvta_generic_to_shared(Rs);
    uint32_t aoff = ((w * 16 + ((l >> 3) & 1) * 8 + (l & 7)) * 68 + ((l >> 4) & 1) * 4) * 4;
    uint32_t boff = ((((l >> 4) & 1) * 8 + (l & 7)) * 68 + ((l >> 3) & 1) * 4) * 4;

    uint32_t qa[8][4];
#pragma unroll
    for (int k8 = 0; k8 < 8; k8++) ldsm4(qa[k8], sQ + aoff + k8 * 32);

    float acc[16][4] = {};
#pragma unroll
    for (int k8 = 0; k8 < 8; k8++)
#pragma unroll
        for (int np = 0; np < 8; np++) {
            uint32_t kb[4];
            ldsm4(kb, sR + boff + np * 16 * 272 + k8 * 32);
            mma8(acc[2 * np],     qa[k8], kb,     acc[2 * np]);
            mma8(acc[2 * np + 1], qa[k8], kb + 2, acc[2 * np + 1]);
        }

    float* out = g_bd + (size_t)bh * S_ * S_;
    int gr = i0 + w * 16 + (l >> 2);
#pragma unroll
    for (int nt = 0; nt < 16; nt++) {
        int gc = t0 + nt * 8 + 2 * (l & 3);
        __stcs((float2*)(out + (size_t)gr * S_ + gc),
               make_float2(acc[nt][0], acc[nt][1]));
        __stcs((float2*)(out + (size_t)(gr + 8) * S_ + gc),
               make_float2(acc[nt][2], acc[nt][3]));
    }
}

// ============================================================
// Fused attention: AC GEMM + rel-shift BD + online softmax + PV.
// BD gather software-pipelined in registers (loaded one phase
// ahead, covered by mma); P via quad shuffle-transpose; 2 CTAs/SM.
// ============================================================
__device__ __forceinline__ float bdval(const float* bd, int i, int j)
{
    if (j <= i)      return __ldcs(bd + (size_t)i * S_ + (S_ - 1 + j - i));
    if (j == i + 1)  return 0.f;
    return __ldcs(bd + (size_t)(i + 1) * S_ + (j - i - 2));
}

__global__ __launch_bounds__(256, 2) void fattn(const float* __restrict__ pbu)
{
    extern __shared__ float sm[];
    float* Qs = sm;                    // 128 x 68 (persistent)
    float* Ks = sm + 8704;             // 128 x 68
    float* Vs = sm + 17408;            // 128 x 72
    int tid = threadIdx.x, l = tid & 31, w = tid >> 5;
    int bh = blockIdx.y, b = bh >> 4, h = bh & 15;
    int i0 = blockIdx.x * 128;
    const float* Qg = g_qkv + (size_t)b * QLD_ + h * 64;
    const float* Kg = Qg + 1024;
    const float* Vg = Qg + 2048;
    const float* bd = g_bd + (size_t)bh * S_ * S_;
    const float* bias = pbu + h * 64;
    uint32_t sQ = (uint32_t)__cvta_generic_to_shared(Qs);
    uint32_t sK = (uint32_t)__cvta_generic_to_shared(Ks);
    uint32_t sV = (uint32_t)__cvta_generic_to_shared(Vs);

    // Q + bias_u -> smem; prefetch K0, V0 as separate cp.async groups
#pragma unroll
    for (int t = 0; t < 8; t++) {
        int idx = tid + t * 256; int r = idx >> 4, c4 = (idx & 15) << 2;
        float4 a4 = *(const float4*)(Qg + (size_t)(i0 + r) * ARS_ + c4);
        float4 u4 = *(const float4*)(bias + c4);
        a4.x += u4.x; a4.y += u4.y; a4.z += u4.z; a4.w += u4.w;
        *(float4*)&Qs[r * 68 + c4] = a4;
    }
#pragma unroll
    for (int t = 0; t < 8; t++) {
        int idx = tid + t * 256; int r = idx >> 4, c4 = (idx & 15) << 2;
        cpa16(sK + (r * 68 + c4) * 4, Kg + (size_t)r * ARS_ + c4);
    }
    cpcommit();
#pragma unroll
    for (int t = 0; t < 8; t++) {
        int idx = tid + t * 256; int r = idx >> 4, c4 = (idx & 15) << 2;
        cpa16(sV + (r * 72 + c4) * 4, Vg + (size_t)r * ARS_ + c4);
    }
    cpcommit();

    uint32_t aoff = ((w * 16 + ((l >> 3) & 1) * 8 + (l & 7)) * 68 + ((l >> 4) & 1) * 4) * 4;
    uint32_t kboff = ((((l >> 4) & 1) * 8 + (l & 7)) * 68 + ((l >> 3) & 1) * 4) * 4;

    float o[8][4] = {};
    float bdbuf[32];
    float mrow0 = -1e30f, mrow1 = -1e30f, lsum0 = 0.f, lsum1 = 0.f;
    int tc = l & 3;
    int lr0 = w * 16 + (l >> 2);
    int row0 = i0 + lr0, row1 = row0 + 8;
    int srcq = (l & ~3) | (tc >> 1);
    bool oddc = tc & 1;
    const float CS = 0.1803368801111204f;   // 0.125 * log2(e)

// prefetch BD values for a 64-col half into registers
#define LDBD(JB)                                                                \
    _Pragma("unroll")                                                           \
    for (int nt = 0; nt < 8; nt++) {                                            \
        int c0 = (JB) + nt * 8 + 2 * tc;                                        \
        bdbuf[nt * 4 + 0] = bdval(bd, row0, c0);                                \
        bdbuf[nt * 4 + 1] = bdval(bd, row0, c0 + 1);                            \
        bdbuf[nt * 4 + 2] = bdval(bd, row1, c0);                                \
        bdbuf[nt * 4 + 3] = bdval(bd, row1, c0 + 1);                            \
    }

    LDBD(0)              // BD for iter0/half0 — overlaps K0/V0 arrival
    __syncthreads();     // Qs visible to ldmatrix

#define AC_MMA(HALF)                                                            \
    _Pragma("unroll")                                                           \
    for (int nt = 0; nt < 8; nt++)                                              \
        p[nt][0] = p[nt][1] = p[nt][2] = p[nt][3] = 0.f;                        \
    _Pragma("unroll")                                                           \
    for (int k8 = 0; k8 < 8; k8++) {                                            \
        uint32_t qf[4];                                                         \
        ldsm4(qf, sQ + aoff + k8 * 32);                                         \
        _Pragma("unroll")                                                       \
        for (int np = 0; np < 4; np++) {                                        \
            uint32_t kb[4];                                                     \
            ldsm4(kb, sK + kboff + ((HALF) * 64 + np * 16) * 272 + k8 * 32);    \
            mma8(p[2 * np],     qf, kb,     p[2 * np]);                         \
            mma8(p[2 * np + 1], qf, kb + 2, p[2 * np + 1]);                     \
        }                                                                       \
    }

#define SOFTMAX_STEP()                                                          \
    {                                                                           \
        float mx0 = -1e30f, mx1 = -1e30f;                                       \
        _Pragma("unroll")                                                       \
        for (int nt = 0; nt < 8; nt++) {                                        \
            float s;                                                            \
            s = (p[nt][0] + bdbuf[nt*4+0]) * CS; p[nt][0] = s; mx0 = fmaxf(mx0, s); \
            s = (p[nt][1] + bdbuf[nt*4+1]) * CS; p[nt][1] = s; mx0 = fmaxf(mx0, s); \
            s = (p[nt][2] + bdbuf[nt*4+2]) * CS; p[nt][2] = s; mx1 = fmaxf(mx1, s); \
            s = (p[nt][3] + bdbuf[nt*4+3]) * CS; p[nt][3] = s; mx1 = fmaxf(mx1, s); \
        }                                                                       \
        mx0 = fmaxf(mx0, __shfl_xor_sync(~0u, mx0, 1));                         \
        mx0 = fmaxf(mx0, __shfl_xor_sync(~0u, mx0, 2));                         \
        mx1 = fmaxf(mx1, __shfl_xor_sync(~0u, mx1, 1));                         \
        mx1 = fmaxf(mx1, __shfl_xor_sync(~0u, mx1, 2));                         \
        float mn0 = fmaxf(mrow0, mx0), mn1 = fmaxf(mrow1, mx1);                 \
        float al0 = ex2(mrow0 - mn0), al1 = ex2(mrow1 - mn1);                   \
        mrow0 = mn0; mrow1 = mn1;                                               \
        float rs0 = 0.f, rs1 = 0.f;                                             \
        _Pragma("unroll")                                                       \
        for (int nt = 0; nt < 8; nt++) {                                        \
            p[nt][0] = ex2(p[nt][0] - mn0); p[nt][1] = ex2(p[nt][1] - mn0);     \
            p[nt][2] = ex2(p[nt][2] - mn1); p[nt][3] = ex2(p[nt][3] - mn1);     \
            rs0 += p[nt][0] + p[nt][1]; rs1 += p[nt][2] + p[nt][3];             \
        }                                                                       \
        rs0 += __shfl_xor_sync(~0u, rs0, 1); rs0 += __shfl_xor_sync(~0u, rs0, 2);\
        rs1 += __shfl_xor_sync(~0u, rs1, 1); rs1 += __shfl_xor_sync(~0u, rs1, 2);\
        lsum0 = lsum0 * al0 + rs0;                                              \
        lsum1 = lsum1 * al1 + rs1;                                              \
        _Pragma("unroll")                                                       \
        for (int nt = 0; nt < 8; nt++) {                                        \
            o[nt][0] *= al0; o[nt][1] *= al0; o[nt][2] *= al1; o[nt][3] *= al1; \
        }                                                                       \
    }

#define TRANS_PV(HALF)                                                          \
    _Pragma("unroll")                                                           \
    for (int k8 = 0; k8 < 8; k8++) {                                            \
        float e00 = __shfl_sync(~0u, p[k8][0], srcq);                           \
        float e01 = __shfl_sync(~0u, p[k8][1], srcq);                           \
        float e10 = __shfl_sync(~0u, p[k8][0], srcq + 2);                       \
        float e11 = __shfl_sync(~0u, p[k8][1], srcq + 2);                       \
        float f00 = __shfl_sync(~0u, p[k8][2], srcq);                           \
        float f01 = __shfl_sync(~0u, p[k8][3], srcq);                           \
        float f10 = __shfl_sync(~0u, p[k8][2], srcq + 2);                       \
        float f11 = __shfl_sync(~0u, p[k8][3], srcq + 2);                       \
        uint32_t af[4];                                                         \
        af[0] = f2u(oddc ? e01 : e00);                                          \
        af[1] = f2u(oddc ? f01 : f00);                                          \
        af[2] = f2u(oddc ? e11 : e10);                                          \
        af[3] = f2u(oddc ? f11 : f10);                                          \
        int kr = (HALF) * 64 + k8 * 8 + tc;                                     \
        _Pragma("unroll")                                                       \
        for (int nt = 0; nt < 8; nt++) {                                        \
            uint32_t vb[2];                                                     \
            vb[0] = f2u(Vs[kr * 72 + nt * 8 + (l >> 2)]);                       \
            vb[1] = f2u(Vs[(kr + 4) * 72 + nt * 8 + (l >> 2)]);                 \
            mma8(o[nt], af, vb, o[nt]);                                         \
        }                                                                       \
    }

    for (int it = 0; it < 16; it++) {
        cpwait<1>();          // K(it) landed; V(it) may be pending
        __syncthreads();      // all threads' K(it) visible

        {   // ---- half 0 (K rows 0-63, V rows 0-63) ----
            float p[8][4];
            AC_MMA(0)
            SOFTMAX_STEP()    // consumes bdbuf (half 0)
            cpwait<0>();      // V(it) complete
            __syncthreads();
            LDBD(it * 128 + 64)   // BD half1 — covered by PV0 + AC1
            TRANS_PV(0)
        }
        {   // ---- half 1 (K rows 64-127, V rows 64-127) ----
            float p[8][4];
            AC_MMA(1)
            SOFTMAX_STEP()    // consumes bdbuf (half 1)
            __syncthreads();  // all warps done with Ks
            if (it + 1 < 16) {
                const float* kn = Kg + (size_t)((it + 1) * 128) * ARS_;
#pragma unroll
                for (int t = 0; t < 8; t++) {
                    int idx = tid + t * 256; int r = idx >> 4, c4 = (idx & 15) << 2;
                    cpa16(sK + (r * 68 + c4) * 4, kn + (size_t)r * ARS_ + c4);
                }
                cpcommit();
                LDBD((it + 1) * 128)   // BD next half0 — covered by PV1 + next AC0
            }
            TRANS_PV(1)
        }
        __syncthreads();      // all warps done reading Vs
        if (it + 1 < 16) {
            const float* vn = Vg + (size_t)((it + 1) * 128) * ARS_;
#pragma unroll
            for (int t = 0; t < 8; t++) {
                int idx = tid + t * 256; int r = idx >> 4, c4 = (idx & 15) << 2;
                cpa16(sV + (r * 72 + c4) * 4, vn + (size_t)r * ARS_ + c4);
            }
            cpcommit();
        }
    }
#undef LDBD
#undef AC_MMA
#undef SOFTMAX_STEP
#undef TRANS_PV

    float inv0 = 1.f / lsum0, inv1 = 1.f / lsum1;
#pragma unroll
    for (int nt = 0; nt < 8; nt++) {
        int c = h * 64 + nt * 8 + 2 * tc;
        *(float2*)(g_att + ((size_t)row0 * B_ + b) * D_ + c) =
            make_float2(o[nt][0] * inv0, o[nt][1] * inv0);
        *(float2*)(g_att + ((size_t)row1 * B_ + b) * D_ + c) =
            make_float2(o[nt][2] * inv1, o[nt][3] * inv1);
    }
}

// ============================================================
// LayerNorm over D=1024 per row.
// ============================================================
__global__ __launch_bounds__(256) void ln_k(const float* __restrict__ gamma,
                                            const float* __restrict__ beta,
                                            float* __restrict__ out)
{
    __shared__ float reds[8], redq[8];
    const float* y = g_y + (size_t)blockIdx.x * D_;
    int tid = threadIdx.x;
    float v[4];
    float s = 0.f, q = 0.f;
#pragma unroll
    for (int t = 0; t < 4; t++) {
        v[t] = y[tid + t * 256];
        s += v[t]; q += v[t] * v[t];
    }
#pragma unroll
    for (int o = 16; o; o >>= 1) {
        s += __shfl_xor_sync(0xffffffffu, s, o);
        q += __shfl_xor_sync(0xffffffffu, q, o);
    }
    if ((tid & 31) == 0) { reds[tid >> 5] = s; redq[tid >> 5] = q; }
    __syncthreads();
    float ts = 0.f, tq = 0.f;
#pragma unroll
    for (int wv = 0; wv < 8; wv++) { ts += reds[wv]; tq += redq[wv]; }
    float mu = ts * (1.f / 1024.f);
    float var = tq * (1.f / 1024.f) - mu * mu;
    float inv = rsqrtf(var + 1e-5f);
    float* op = out + (size_t)blockIdx.x * D_;
#pragma unroll
    for (int t = 0; t < 4; t++) {
        int c = tid + t * 256;
        op[c] = (v[t] - mu) * inv * gamma[c] + beta[c];
    }
}

// ============================================================
extern "C" void kernel_launch(void* const* d_in, const int* in_sizes, int n_in,
                              void* d_out, int out_size)
{
    const float* x    = (const float*)d_in[0];
    const float* pe   = (const float*)d_in[1];
    const float* pbu  = (const float*)d_in[2];
    const float* pbv  = (const float*)d_in[3];
    const float* Wqkv = (const float*)d_in[4];
    const float* Wrel = (const float*)d_in[5];
    const float* Wo   = (const float*)d_in[6];
    const float* gam  = (const float*)d_in[7];
    const float* bet  = (const float*)d_in[8];
    float* out = (float*)d_out;

    const int PG_SMEM = 71680;     // (9216 + 8704) * 4
    const int BD_SMEM = 69632;     // 2 * 128*68 * 4
    const int FA_SMEM = 106496;    // (8704 + 8704 + 9216) * 4
    cudaFuncSetAttribute(pgemm<0>, cudaFuncAttributeMaxDynamicSharedMemorySize, PG_SMEM);
    cudaFuncSetAttribute(pgemm<1>, cudaFuncAttributeMaxDynamicSharedMemorySize, PG_SMEM);
    cudaFuncSetAttribute(pgemm<2>, cudaFuncAttributeMaxDynamicSharedMemorySize, PG_SMEM);
    cudaFuncSetAttribute(bd_gemm,  cudaFuncAttributeMaxDynamicSharedMemorySize, BD_SMEM);
    cudaFuncSetAttribute(fattn,    cudaFuncAttributeMaxDynamicSharedMemorySize, FA_SMEM);

    // 1) qkv = x @ W_qkv
    pgemm<0><<<dim3(24, 32), 256, PG_SMEM>>>(x, Wqkv, nullptr, 3072);
    // 2) r = pos_emb @ W_relemb
    pgemm<1><<<dim3(8, 16), 256, PG_SMEM>>>(pe, Wrel, nullptr, 1024);
    // 3) Draw = (q + pbv) @ r^T per (b,h)
    bd_gemm<<<dim3(16, 16, 32), 256, BD_SMEM>>>(pbv);
    // 4) fused: scores + rel-shift + softmax + PV
    fattn<<<dim3(16, 32), 256, FA_SMEM>>>(pbu);
    // 5) y = x + attn_vec @ W_o
    pgemm<2><<<dim3(8, 32), 256, PG_SMEM>>>(nullptr, Wo, x, 1024);
    // 6) layernorm
    ln_k<<<4096, 256>>>(gam, bet, out);
}

// round 7
// speedup vs baseline: 4.1087x; 1.3043x over previous
#include <cuda_runtime.h>
#include <cuda_fp16.h>
#include <stdint.h>

#define S_    2048
#define B_    2
#define D_    1024
#define H_    16
#define BH_   32
#define ROWS_ 4096
#define QLD_  3072
#define ARS_  6144   // B_*QLD_ : stride between seq rows in g_qkv

// ---- scratch (static device globals; no allocation) ----
__device__ float  g_qkv[(size_t)ROWS_ * 3072];         // [s*B+b][q|k|(v unused)]
__device__ __half g_vh [(size_t)ROWS_ * 1024];         // V in fp16 [s*B+b][h*64+d]
__device__ float  g_r  [(size_t)S_ * D_];              // [t][h*64+d]
__device__ float  g_bd [(size_t)BH_ * S_ * S_];        // Draw per (b,h)
__device__ float  g_att[(size_t)ROWS_ * D_];           // attn_vec
__device__ float  g_y  [(size_t)ROWS_ * D_];           // x + attn_out

// ---------------- mma / cp.async / ldmatrix helpers ----------------
__device__ __forceinline__ void mma8(float* d, const uint32_t* a,
                                     const uint32_t* b, const float* c) {
    asm volatile(
        "mma.sync.aligned.m16n8k8.row.col.f32.tf32.tf32.f32 "
        "{%0,%1,%2,%3}, {%4,%5,%6,%7}, {%8,%9}, {%10,%11,%12,%13};\n"
        : "=f"(d[0]), "=f"(d[1]), "=f"(d[2]), "=f"(d[3])
        : "r"(a[0]), "r"(a[1]), "r"(a[2]), "r"(a[3]), "r"(b[0]), "r"(b[1]),
          "f"(c[0]), "f"(c[1]), "f"(c[2]), "f"(c[3]));
}
__device__ __forceinline__ void mma16h(float* d, const uint32_t* a,
                                       const uint32_t* b, const float* c) {
    asm volatile(
        "mma.sync.aligned.m16n8k16.row.col.f32.f16.f16.f32 "
        "{%0,%1,%2,%3}, {%4,%5,%6,%7}, {%8,%9}, {%10,%11,%12,%13};\n"
        : "=f"(d[0]), "=f"(d[1]), "=f"(d[2]), "=f"(d[3])
        : "r"(a[0]), "r"(a[1]), "r"(a[2]), "r"(a[3]), "r"(b[0]), "r"(b[1]),
          "f"(c[0]), "f"(c[1]), "f"(c[2]), "f"(c[3]));
}
__device__ __forceinline__ uint32_t f2u(float x) { return __float_as_uint(x); }
__device__ __forceinline__ uint32_t h2(float lo, float hi) {
    uint32_t d;
    asm("cvt.rn.f16x2.f32 %0, %1, %2;\n" : "=r"(d) : "f"(hi), "f"(lo));
    return d;   // d.lo = lo, d.hi = hi
}
__device__ __forceinline__ void cpa16(uint32_t s, const void* g) {
    asm volatile("cp.async.cg.shared.global [%0], [%1], 16;\n" :: "r"(s), "l"(g));
}
__device__ __forceinline__ void cpcommit() { asm volatile("cp.async.commit_group;\n"); }
template <int N> __device__ __forceinline__ void cpwait() {
    asm volatile("cp.async.wait_group %0;\n" :: "n"(N));
}
__device__ __forceinline__ void ldsm4(uint32_t* r, uint32_t a) {
    asm volatile("ldmatrix.sync.aligned.m8n8.x4.shared.b16 {%0,%1,%2,%3}, [%4];\n"
        : "=r"(r[0]), "=r"(r[1]), "=r"(r[2]), "=r"(r[3]) : "r"(a));
}
__device__ __forceinline__ void ldsm4t(uint32_t* r, uint32_t a) {
    asm volatile("ldmatrix.sync.aligned.m8n8.x4.trans.shared.b16 {%0,%1,%2,%3}, [%4];\n"
        : "=r"(r[0]), "=r"(r[1]), "=r"(r[2]), "=r"(r[3]) : "r"(a));
}
__device__ __forceinline__ float ex2(float x) {
    float y; asm("ex2.approx.f32 %0, %1;" : "=f"(y) : "f"(x)); return y;
}

// ============================================================
// Projection GEMM, K=1024 fixed, tile 128x128x32, cp.async 2-stage.
// MODE 0: g_qkv (q,k cols) / g_vh fp16 (v cols)
// MODE 1: g_r = A@B    MODE 2: g_y = g_att@B + Xres
// ============================================================
template <int MODE>
__global__ __launch_bounds__(256) void pgemm(const float* __restrict__ A,
                                             const float* __restrict__ Bw,
                                             const float* __restrict__ Xres,
                                             int N)
{
    extern __shared__ float sm[];
    float* As = sm;               // 2 x 128 x 36
    float* Bs = sm + 9216;        // 2 x 32  x 136
    const float* Ap = (MODE == 2) ? (const float*)g_att : A;
    float* C = (MODE == 0) ? g_qkv : (MODE == 1) ? g_r : g_y;

    int tid = threadIdx.x, l = tid & 31, w = tid >> 5, wm = w >> 1, wn = w & 1;
    size_t m0 = (size_t)blockIdx.y * 128, n0 = (size_t)blockIdx.x * 128;
    uint32_t sA = (uint32_t)__cvta_generic_to_shared(As);
    uint32_t sB = (uint32_t)__cvta_generic_to_shared(Bs);

    float acc[2][8][4] = {};

#define STAGE(IT, BUF)                                                          \
    {                                                                           \
        int kk = (IT) * 32;                                                     \
        uint32_t ab = sA + (BUF) * 4608 * 4;                                    \
        _Pragma("unroll")                                                       \
        for (int t = 0; t < 4; t++) {                                           \
            int idx = tid + t * 256; int r = idx >> 3, c4 = (idx & 7) << 2;     \
            cpa16(ab + (r * 36 + c4) * 4, Ap + (m0 + r) * 1024 + kk + c4);      \
        }                                                                       \
        uint32_t bb = sB + (BUF) * 4352 * 4;                                    \
        _Pragma("unroll")                                                       \
        for (int t = 0; t < 4; t++) {                                           \
            int idx = tid + t * 256; int r = idx >> 5, c4 = (idx & 31) << 2;    \
            cpa16(bb + (r * 136 + c4) * 4, Bw + (size_t)(kk + r) * N + n0 + c4);\
        }                                                                       \
        cpcommit();                                                             \
    }

    STAGE(0, 0);
    for (int it = 0; it < 32; it++) {
        int buf = it & 1;
        if (it + 1 < 32) { STAGE(it + 1, buf ^ 1); cpwait<1>(); }
        else             { cpwait<0>(); }
        __syncthreads();
        const float* As_ = As + buf * 4608;
        const float* Bs_ = Bs + buf * 4352;
#pragma unroll
        for (int k8 = 0; k8 < 4; k8++) {
            uint32_t a[2][4];
#pragma unroll
            for (int mt = 0; mt < 2; mt++) {
                int r = wm * 32 + mt * 16 + (l >> 2);
                a[mt][0] = f2u(As_[r * 36 + k8 * 8 + (l & 3)]);
                a[mt][1] = f2u(As_[(r + 8) * 36 + k8 * 8 + (l & 3)]);
                a[mt][2] = f2u(As_[r * 36 + k8 * 8 + (l & 3) + 4]);
                a[mt][3] = f2u(As_[(r + 8) * 36 + k8 * 8 + (l & 3) + 4]);
            }
#pragma unroll
            for (int nt = 0; nt < 8; nt++) {
                uint32_t bf[2];
                int cb = wn * 64 + nt * 8 + (l >> 2);
                bf[0] = f2u(Bs_[(k8 * 8 + (l & 3)) * 136 + cb]);
                bf[1] = f2u(Bs_[(k8 * 8 + (l & 3) + 4) * 136 + cb]);
#pragma unroll
                for (int mt = 0; mt < 2; mt++)
                    mma8(acc[mt][nt], a[mt], bf, acc[mt][nt]);
            }
        }
        __syncthreads();
    }
#undef STAGE

    if (MODE == 0 && n0 >= 2048) {
        // V columns: write fp16 copy only (f32 V is never read)
#pragma unroll
        for (int mt = 0; mt < 2; mt++) {
            size_t r0 = m0 + wm * 32 + mt * 16 + (l >> 2);
#pragma unroll
            for (int nt = 0; nt < 8; nt++) {
                size_t c = (n0 - 2048) + wn * 64 + nt * 8 + 2 * (l & 3);
                *(__half2*)(g_vh + r0 * 1024 + c) =
                    __floats2half2_rn(acc[mt][nt][0], acc[mt][nt][1]);
                *(__half2*)(g_vh + (r0 + 8) * 1024 + c) =
                    __floats2half2_rn(acc[mt][nt][2], acc[mt][nt][3]);
            }
        }
        return;
    }
#pragma unroll
    for (int mt = 0; mt < 2; mt++) {
        size_t r0 = m0 + wm * 32 + mt * 16 + (l >> 2);
#pragma unroll
        for (int nt = 0; nt < 8; nt++) {
            size_t c = n0 + wn * 64 + nt * 8 + 2 * (l & 3);
            float2 v0 = make_float2(acc[mt][nt][0], acc[mt][nt][1]);
            float2 v1 = make_float2(acc[mt][nt][2], acc[mt][nt][3]);
            if (MODE == 2) {
                float2 x0 = *(const float2*)(Xres + r0 * N + c);
                float2 x1 = *(const float2*)(Xres + (r0 + 8) * N + c);
                v0.x += x0.x; v0.y += x0.y; v1.x += x1.x; v1.y += x1.y;
            }
            *(float2*)(C + r0 * N + c) = v0;
            *(float2*)(C + (r0 + 8) * N + c) = v1;
        }
    }
}

// ============================================================
// Draw = (q + pos_bias_v) @ r^T per (b,h). 128x128, K=64, ldmatrix.
// Streaming stores (written once, read once later).
// ============================================================
__global__ __launch_bounds__(256, 2) void bd_gemm(const float* __restrict__ pbv)
{
    extern __shared__ float sm[];
    float* Qs = sm;               // 128 x 68
    float* Rs = sm + 8704;        // 128 x 68
    int tid = threadIdx.x, l = tid & 31, w = tid >> 5;
    int bh = blockIdx.z, b = bh >> 4, h = bh & 15;
    int i0 = blockIdx.y * 128, t0 = blockIdx.x * 128;
    const float* Qg = g_qkv + (size_t)b * QLD_ + h * 64;
    const float* Rg = g_r + h * 64;
    const float* bias = pbv + h * 64;

#pragma unroll
    for (int t = 0; t < 8; t++) {
        int idx = tid + t * 256; int r = idx >> 4, c4 = (idx & 15) << 2;
        float4 a4 = *(const float4*)(Qg + (size_t)(i0 + r) * ARS_ + c4);
        float4 u4 = *(const float4*)(bias + c4);
        a4.x += u4.x; a4.y += u4.y; a4.z += u4.z; a4.w += u4.w;
        *(float4*)&Qs[r * 68 + c4] = a4;
        *(float4*)&Rs[r * 68 + c4] = *(const float4*)(Rg + (size_t)(t0 + r) * D_ + c4);
    }
    __syncthreads();

    uint32_t sQ = (uint32_t)__cvta_generic_to_shared(Qs);
    uint32_t sR = (uint32_t)__cvta_generic_to_shared(Rs);
    uint32_t aoff = ((w * 16 + ((l >> 3) & 1) * 8 + (l & 7)) * 68 + ((l >> 4) & 1) * 4) * 4;
    uint32_t boff = ((((l >> 4) & 1) * 8 + (l & 7)) * 68 + ((l >> 3) & 1) * 4) * 4;

    uint32_t qa[8][4];
#pragma unroll
    for (int k8 = 0; k8 < 8; k8++) ldsm4(qa[k8], sQ + aoff + k8 * 32);

    float acc[16][4] = {};
#pragma unroll
    for (int k8 = 0; k8 < 8; k8++)
#pragma unroll
        for (int np = 0; np < 8; np++) {
            uint32_t kb[4];
            ldsm4(kb, sR + boff + np * 16 * 272 + k8 * 32);
            mma8(acc[2 * np],     qa[k8], kb,     acc[2 * np]);
            mma8(acc[2 * np + 1], qa[k8], kb + 2, acc[2 * np + 1]);
        }

    float* out = g_bd + (size_t)bh * S_ * S_;
    int gr = i0 + w * 16 + (l >> 2);
#pragma unroll
    for (int nt = 0; nt < 16; nt++) {
        int gc = t0 + nt * 8 + 2 * (l & 3);
        __stcs((float2*)(out + (size_t)gr * S_ + gc),
               make_float2(acc[nt][0], acc[nt][1]));
        __stcs((float2*)(out + (size_t)(gr + 8) * S_ + gc),
               make_float2(acc[nt][2], acc[nt][3]));
    }
}

// ============================================================
// Fused attention. AC in tf32; P->fp16 in registers (acc layout
// == fp16 A-frag layout, no shuffles); PV in fp16 m16n8k16 with
// V fp16 via ldmatrix.trans. BD gather pipelined in registers.
// ============================================================
__device__ __forceinline__ float bdval(const float* bd, int i, int j)
{
    if (j <= i)      return __ldcs(bd + (size_t)i * S_ + (S_ - 1 + j - i));
    if (j == i + 1)  return 0.f;
    return __ldcs(bd + (size_t)(i + 1) * S_ + (j - i - 2));
}

__global__ __launch_bounds__(256, 2) void fattn(const float* __restrict__ pbu)
{
    extern __shared__ float sm[];
    float*  Qs  = sm;                       // 128 x 68 f32 (persistent)
    float*  Ks  = sm + 8704;                // 128 x 68 f32
    __half* Vsh = (__half*)(sm + 17408);    // 128 x 72 fp16
    int tid = threadIdx.x, l = tid & 31, w = tid >> 5;
    int bh = blockIdx.y, b = bh >> 4, h = bh & 15;
    int i0 = blockIdx.x * 128;
    const float* Qg = g_qkv + (size_t)b * QLD_ + h * 64;
    const float* Kg = Qg + 1024;
    const __half* Vg = g_vh + (size_t)b * 1024 + h * 64;   // row stride 2048
    const float* bd = g_bd + (size_t)bh * S_ * S_;
    const float* bias = pbu + h * 64;
    uint32_t sQ = (uint32_t)__cvta_generic_to_shared(Qs);
    uint32_t sK = (uint32_t)__cvta_generic_to_shared(Ks);
    uint32_t sV = (uint32_t)__cvta_generic_to_shared(Vsh);

    // Q + bias_u -> smem; prefetch K0 (group), V0 (group)
#pragma unroll
    for (int t = 0; t < 8; t++) {
        int idx = tid + t * 256; int r = idx >> 4, c4 = (idx & 15) << 2;
        float4 a4 = *(const float4*)(Qg + (size_t)(i0 + r) * ARS_ + c4);
        float4 u4 = *(const float4*)(bias + c4);
        a4.x += u4.x; a4.y += u4.y; a4.z += u4.z; a4.w += u4.w;
        *(float4*)&Qs[r * 68 + c4] = a4;
    }
#pragma unroll
    for (int t = 0; t < 8; t++) {
        int idx = tid + t * 256; int r = idx >> 4, c4 = (idx & 15) << 2;
        cpa16(sK + (r * 68 + c4) * 4, Kg + (size_t)r * ARS_ + c4);
    }
    cpcommit();
#pragma unroll
    for (int t = 0; t < 4; t++) {
        int idx = tid + t * 256; int r = idx >> 3, c8 = (idx & 7) << 3;
        cpa16(sV + (r * 72 + c8) * 2, Vg + (size_t)r * 2048 + c8);
    }
    cpcommit();

    uint32_t aoff = ((w * 16 + ((l >> 3) & 1) * 8 + (l & 7)) * 68 + ((l >> 4) & 1) * 4) * 4;
    uint32_t kboff = ((((l >> 4) & 1) * 8 + (l & 7)) * 68 + ((l >> 3) & 1) * 4) * 4;
    uint32_t vrbase = (uint32_t)((l & 7) + ((l >> 3) & 1) * 8);   // row within k16 tile
    uint32_t vcoff  = (uint32_t)((l >> 4) * 8);                   // col offset (8-col half)

    float o[8][4] = {};
    float bdbuf[32];
    float mrow0 = -1e30f, mrow1 = -1e30f, lsum0 = 0.f, lsum1 = 0.f;
    int tc = l & 3;
    int lr0 = w * 16 + (l >> 2);
    int row0 = i0 + lr0, row1 = row0 + 8;
    const float CS = 0.1803368801111204f;   // 0.125 * log2(e)

#define LDBD(JB)                                                                \
    _Pragma("unroll")                                                           \
    for (int nt = 0; nt < 8; nt++) {                                            \
        int c0 = (JB) + nt * 8 + 2 * tc;                                        \
        bdbuf[nt * 4 + 0] = bdval(bd, row0, c0);                                \
        bdbuf[nt * 4 + 1] = bdval(bd, row0, c0 + 1);                            \
        bdbuf[nt * 4 + 2] = bdval(bd, row1, c0);                                \
        bdbuf[nt * 4 + 3] = bdval(bd, row1, c0 + 1);                            \
    }

    LDBD(0)              // BD for iter0/half0 — overlaps K0/V0 arrival
    __syncthreads();     // Qs visible to ldmatrix

#define AC_MMA(HALF)                                                            \
    _Pragma("unroll")                                                           \
    for (int nt = 0; nt < 8; nt++)                                              \
        p[nt][0] = p[nt][1] = p[nt][2] = p[nt][3] = 0.f;                        \
    _Pragma("unroll")                                                           \
    for (int k8 = 0; k8 < 8; k8++) {                                            \
        uint32_t qf[4];                                                         \
        ldsm4(qf, sQ + aoff + k8 * 32);                                         \
        _Pragma("unroll")                                                       \
        for (int np = 0; np < 4; np++) {                                        \
            uint32_t kb[4];                                                     \
            ldsm4(kb, sK + kboff + ((HALF) * 64 + np * 16) * 272 + k8 * 32);    \
            mma8(p[2 * np],     qf, kb,     p[2 * np]);                         \
            mma8(p[2 * np + 1], qf, kb + 2, p[2 * np + 1]);                     \
        }                                                                       \
    }

#define SOFTMAX_STEP()                                                          \
    {                                                                           \
        float mx0 = -1e30f, mx1 = -1e30f;                                       \
        _Pragma("unroll")                                                       \
        for (int nt = 0; nt < 8; nt++) {                                        \
            float s;                                                            \
            s = (p[nt][0] + bdbuf[nt*4+0]) * CS; p[nt][0] = s; mx0 = fmaxf(mx0, s); \
            s = (p[nt][1] + bdbuf[nt*4+1]) * CS; p[nt][1] = s; mx0 = fmaxf(mx0, s); \
            s = (p[nt][2] + bdbuf[nt*4+2]) * CS; p[nt][2] = s; mx1 = fmaxf(mx1, s); \
            s = (p[nt][3] + bdbuf[nt*4+3]) * CS; p[nt][3] = s; mx1 = fmaxf(mx1, s); \
        }                                                                       \
        mx0 = fmaxf(mx0, __shfl_xor_sync(~0u, mx0, 1));                         \
        mx0 = fmaxf(mx0, __shfl_xor_sync(~0u, mx0, 2));                         \
        mx1 = fmaxf(mx1, __shfl_xor_sync(~0u, mx1, 1));                         \
        mx1 = fmaxf(mx1, __shfl_xor_sync(~0u, mx1, 2));                         \
        float mn0 = fmaxf(mrow0, mx0), mn1 = fmaxf(mrow1, mx1);                 \
        float al0 = ex2(mrow0 - mn0), al1 = ex2(mrow1 - mn1);                   \
        mrow0 = mn0; mrow1 = mn1;                                               \
        float rs0 = 0.f, rs1 = 0.f;                                             \
        _Pragma("unroll")                                                       \
        for (int nt = 0; nt < 8; nt++) {                                        \
            p[nt][0] = ex2(p[nt][0] - mn0); p[nt][1] = ex2(p[nt][1] - mn0);     \
            p[nt][2] = ex2(p[nt][2] - mn1); p[nt][3] = ex2(p[nt][3] - mn1);     \
            rs0 += p[nt][0] + p[nt][1]; rs1 += p[nt][2] + p[nt][3];             \
        }                                                                       \
        rs0 += __shfl_xor_sync(~0u, rs0, 1); rs0 += __shfl_xor_sync(~0u, rs0, 2);\
        rs1 += __shfl_xor_sync(~0u, rs1, 1); rs1 += __shfl_xor_sync(~0u, rs1, 2);\
        lsum0 = lsum0 * al0 + rs0;                                              \
        lsum1 = lsum1 * al1 + rs1;                                              \
        _Pragma("unroll")                                                       \
        for (int nt = 0; nt < 8; nt++) {                                        \
            o[nt][0] *= al0; o[nt][1] *= al0; o[nt][2] *= al1; o[nt][3] *= al1; \
        }                                                                       \
    }

// P (f32 acc layout) -> fp16 A-frags: af[ks] covers k-cols 16ks..16ks+15
#define CVT_P()                                                                 \
    uint32_t af[4][4];                                                          \
    _Pragma("unroll")                                                           \
    for (int ks = 0; ks < 4; ks++) {                                            \
        af[ks][0] = h2(p[2*ks][0],   p[2*ks][1]);                               \
        af[ks][1] = h2(p[2*ks][2],   p[2*ks][3]);                               \
        af[ks][2] = h2(p[2*ks+1][0], p[2*ks+1][1]);                             \
        af[ks][3] = h2(p[2*ks+1][2], p[2*ks+1][3]);                             \
    }

#define PV16(HALF)                                                              \
    _Pragma("unroll")                                                           \
    for (int ks = 0; ks < 4; ks++) {                                            \
        uint32_t vrow = (uint32_t)((HALF) * 64 + ks * 16) + vrbase;             \
        _Pragma("unroll")                                                       \
        for (int ntt = 0; ntt < 4; ntt++) {                                     \
            uint32_t vb[4];                                                     \
            ldsm4t(vb, sV + (vrow * 72 + ntt * 16 + vcoff) * 2);                \
            mma16h(o[2*ntt],   af[ks], vb,   o[2*ntt]);                         \
            mma16h(o[2*ntt+1], af[ks], vb+2, o[2*ntt+1]);                       \
        }                                                                       \
    }

    for (int it = 0; it < 16; it++) {
        cpwait<1>();          // K(it) landed; V(it) may be pending
        __syncthreads();      // all threads' K(it) visible

        {   // ---- half 0 ----
            float p[8][4];
            AC_MMA(0)
            SOFTMAX_STEP()
            CVT_P()           // p dead after this
            cpwait<0>();      // V(it) complete
            __syncthreads();
            LDBD(it * 128 + 64)   // BD half1 — covered by PV0 + AC1
            PV16(0)
        }
        {   // ---- half 1 ----
            float p[8][4];
            AC_MMA(1)
            SOFTMAX_STEP()
            CVT_P()
            __syncthreads();  // all warps done with Ks
            if (it + 1 < 16) {
                const float* kn = Kg + (size_t)((it + 1) * 128) * ARS_;
#pragma unroll
                for (int t = 0; t < 8; t++) {
                    int idx = tid + t * 256; int r = idx >> 4, c4 = (idx & 15) << 2;
                    cpa16(sK + (r * 68 + c4) * 4, kn + (size_t)r * ARS_ + c4);
                }
                cpcommit();
                LDBD((it + 1) * 128)   // BD next half0 — covered by PV1 + next AC0
            }
            PV16(1)
        }
        __syncthreads();      // all warps done reading Vs
        if (it + 1 < 16) {
            const __half* vn = Vg + (size_t)((it + 1) * 128) * 2048;
#pragma unroll
            for (int t = 0; t < 4; t++) {
                int idx = tid + t * 256; int r = idx >> 3, c8 = (idx & 7) << 3;
                cpa16(sV + (r * 72 + c8) * 2, vn + (size_t)r * 2048 + c8);
            }
            cpcommit();
        }
    }
#undef LDBD
#undef AC_MMA
#undef SOFTMAX_STEP
#undef CVT_P
#undef PV16

    float inv0 = 1.f / lsum0, inv1 = 1.f / lsum1;
#pragma unroll
    for (int nt = 0; nt < 8; nt++) {
        int c = h * 64 + nt * 8 + 2 * tc;
        *(float2*)(g_att + ((size_t)row0 * B_ + b) * D_ + c) =
            make_float2(o[nt][0] * inv0, o[nt][1] * inv0);
        *(float2*)(g_att + ((size_t)row1 * B_ + b) * D_ + c) =
            make_float2(o[nt][2] * inv1, o[nt][3] * inv1);
    }
}

// ============================================================
// LayerNorm over D=1024 per row.
// ============================================================
__global__ __launch_bounds__(256) void ln_k(const float* __restrict__ gamma,
                                            const float* __restrict__ beta,
                                            float* __restrict__ out)
{
    __shared__ float reds[8], redq[8];
    const float* y = g_y + (size_t)blockIdx.x * D_;
    int tid = threadIdx.x;
    float v[4];
    float s = 0.f, q = 0.f;
#pragma unroll
    for (int t = 0; t < 4; t++) {
        v[t] = y[tid + t * 256];
        s += v[t]; q += v[t] * v[t];
    }
#pragma unroll
    for (int o = 16; o; o >>= 1) {
        s += __shfl_xor_sync(0xffffffffu, s, o);
        q += __shfl_xor_sync(0xffffffffu, q, o);
    }
    if ((tid & 31) == 0) { reds[tid >> 5] = s; redq[tid >> 5] = q; }
    __syncthreads();
    float ts = 0.f, tq = 0.f;
#pragma unroll
    for (int wv = 0; wv < 8; wv++) { ts += reds[wv]; tq += redq[wv]; }
    float mu = ts * (1.f / 1024.f);
    float var = tq * (1.f / 1024.f) - mu * mu;
    float inv = rsqrtf(var + 1e-5f);
    float* op = out + (size_t)blockIdx.x * D_;
#pragma unroll
    for (int t = 0; t < 4; t++) {
        int c = tid + t * 256;
        op[c] = (v[t] - mu) * inv * gamma[c] + beta[c];
    }
}

// ============================================================
extern "C" void kernel_launch(void* const* d_in, const int* in_sizes, int n_in,
                              void* d_out, int out_size)
{
    const float* x    = (const float*)d_in[0];
    const float* pe   = (const float*)d_in[1];
    const float* pbu  = (const float*)d_in[2];
    const float* pbv  = (const float*)d_in[3];
    const float* Wqkv = (const float*)d_in[4];
    const float* Wrel = (const float*)d_in[5];
    const float* Wo   = (const float*)d_in[6];
    const float* gam  = (const float*)d_in[7];
    const float* bet  = (const float*)d_in[8];
    float* out = (float*)d_out;

    const int PG_SMEM = 71680;     // (9216 + 8704) * 4
    const int BD_SMEM = 69632;     // 2 * 128*68 * 4
    const int FA_SMEM = 88064;     // (8704 + 8704) * 4 + 128*72*2
    cudaFuncSetAttribute(pgemm<0>, cudaFuncAttributeMaxDynamicSharedMemorySize, PG_SMEM);
    cudaFuncSetAttribute(pgemm<1>, cudaFuncAttributeMaxDynamicSharedMemorySize, PG_SMEM);
    cudaFuncSetAttribute(pgemm<2>, cudaFuncAttributeMaxDynamicSharedMemorySize, PG_SMEM);
    cudaFuncSetAttribute(bd_gemm,  cudaFuncAttributeMaxDynamicSharedMemorySize, BD_SMEM);
    cudaFuncSetAttribute(fattn,    cudaFuncAttributeMaxDynamicSharedMemorySize, FA_SMEM);

    // 1) qkv = x @ W_qkv  (q,k -> f32; v -> fp16)
    pgemm<0><<<dim3(24, 32), 256, PG_SMEM>>>(x, Wqkv, nullptr, 3072);
    // 2) r = pos_emb @ W_relemb
    pgemm<1><<<dim3(8, 16), 256, PG_SMEM>>>(pe, Wrel, nullptr, 1024);
    // 3) Draw = (q + pbv) @ r^T per (b,h)
    bd_gemm<<<dim3(16, 16, 32), 256, BD_SMEM>>>(pbv);
    // 4) fused: scores + rel-shift + softmax + PV
    fattn<<<dim3(16, 32), 256, FA_SMEM>>>(pbu);
    // 5) y = x + attn_vec @ W_o
    pgemm<2><<<dim3(8, 32), 256, PG_SMEM>>>(nullptr, Wo, x, 1024);
    // 6) layernorm
    ln_k<<<4096, 256>>>(gam, bet, out);
}

// round 8
// speedup vs baseline: 4.4467x; 1.0823x over previous
#include <cuda_runtime.h>
#include <cuda_fp16.h>
#include <stdint.h>

#define S_    2048
#define B_    2
#define D_    1024
#define H_    16
#define BH_   32
#define ROWS_ 4096
#define QLD_  3072
#define ARS_  6144   // B_*QLD_ : stride between seq rows in g_qkv

// ---- scratch (static device globals; no allocation) ----
__device__ float  g_qkv[(size_t)ROWS_ * 3072];         // q cols f32 (k,v blocks unused)
__device__ __half g_kh [(size_t)ROWS_ * 1024];         // K fp16 [s*B+b][h*64+d]
__device__ __half g_vh [(size_t)ROWS_ * 1024];         // V fp16 [s*B+b][h*64+d]
__device__ float  g_r  [(size_t)S_ * D_];              // [t][h*64+d]
__device__ float  g_bd [(size_t)BH_ * S_ * S_];        // Draw per (b,h)
__device__ float  g_att[(size_t)ROWS_ * D_];           // attn_vec
__device__ float  g_y  [(size_t)ROWS_ * D_];           // x + attn_out

// ---------------- mma / cp.async / ldmatrix helpers ----------------
__device__ __forceinline__ void mma8(float* d, const uint32_t* a,
                                     const uint32_t* b, const float* c) {
    asm volatile(
        "mma.sync.aligned.m16n8k8.row.col.f32.tf32.tf32.f32 "
        "{%0,%1,%2,%3}, {%4,%5,%6,%7}, {%8,%9}, {%10,%11,%12,%13};\n"
        : "=f"(d[0]), "=f"(d[1]), "=f"(d[2]), "=f"(d[3])
        : "r"(a[0]), "r"(a[1]), "r"(a[2]), "r"(a[3]), "r"(b[0]), "r"(b[1]),
          "f"(c[0]), "f"(c[1]), "f"(c[2]), "f"(c[3]));
}
__device__ __forceinline__ void mma16h(float* d, const uint32_t* a,
                                       const uint32_t* b, const float* c) {
    asm volatile(
        "mma.sync.aligned.m16n8k16.row.col.f32.f16.f16.f32 "
        "{%0,%1,%2,%3}, {%4,%5,%6,%7}, {%8,%9}, {%10,%11,%12,%13};\n"
        : "=f"(d[0]), "=f"(d[1]), "=f"(d[2]), "=f"(d[3])
        : "r"(a[0]), "r"(a[1]), "r"(a[2]), "r"(a[3]), "r"(b[0]), "r"(b[1]),
          "f"(c[0]), "f"(c[1]), "f"(c[2]), "f"(c[3]));
}
__device__ __forceinline__ uint32_t f2u(float x) { return __float_as_uint(x); }
__device__ __forceinline__ uint32_t h2(float lo, float hi) {
    uint32_t d;
    asm("cvt.rn.f16x2.f32 %0, %1, %2;\n" : "=r"(d) : "f"(hi), "f"(lo));
    return d;   // d.lo = lo, d.hi = hi
}
__device__ __forceinline__ void cpa16(uint32_t s, const void* g) {
    asm volatile("cp.async.cg.shared.global [%0], [%1], 16;\n" :: "r"(s), "l"(g));
}
__device__ __forceinline__ void cpcommit() { asm volatile("cp.async.commit_group;\n"); }
template <int N> __device__ __forceinline__ void cpwait() {
    asm volatile("cp.async.wait_group %0;\n" :: "n"(N));
}
__device__ __forceinline__ void ldsm4(uint32_t* r, uint32_t a) {
    asm volatile("ldmatrix.sync.aligned.m8n8.x4.shared.b16 {%0,%1,%2,%3}, [%4];\n"
        : "=r"(r[0]), "=r"(r[1]), "=r"(r[2]), "=r"(r[3]) : "r"(a));
}
__device__ __forceinline__ void ldsm4t(uint32_t* r, uint32_t a) {
    asm volatile("ldmatrix.sync.aligned.m8n8.x4.trans.shared.b16 {%0,%1,%2,%3}, [%4];\n"
        : "=r"(r[0]), "=r"(r[1]), "=r"(r[2]), "=r"(r[3]) : "r"(a));
}
__device__ __forceinline__ float ex2(float x) {
    float y; asm("ex2.approx.f32 %0, %1;" : "=f"(y) : "f"(x)); return y;
}

// ============================================================
// Projection GEMM, K=1024 fixed, tile 128x128x32, cp.async 2-stage.
// MODE 0: q cols -> g_qkv f32, K cols -> g_kh fp16, V cols -> g_vh fp16
// MODE 1: g_r = A@B    MODE 2: g_y = g_att@B + Xres
// ============================================================
template <int MODE>
__global__ __launch_bounds__(256) void pgemm(const float* __restrict__ A,
                                             const float* __restrict__ Bw,
                                             const float* __restrict__ Xres,
                                             int N)
{
    extern __shared__ float sm[];
    float* As = sm;               // 2 x 128 x 36
    float* Bs = sm + 9216;        // 2 x 32  x 136
    const float* Ap = (MODE == 2) ? (const float*)g_att : A;
    float* C = (MODE == 0) ? g_qkv : (MODE == 1) ? g_r : g_y;

    int tid = threadIdx.x, l = tid & 31, w = tid >> 5, wm = w >> 1, wn = w & 1;
    size_t m0 = (size_t)blockIdx.y * 128, n0 = (size_t)blockIdx.x * 128;
    uint32_t sA = (uint32_t)__cvta_generic_to_shared(As);
    uint32_t sB = (uint32_t)__cvta_generic_to_shared(Bs);

    float acc[2][8][4] = {};

#define STAGE(IT, BUF)                                                          \
    {                                                                           \
        int kk = (IT) * 32;                                                     \
        uint32_t ab = sA + (BUF) * 4608 * 4;                                    \
        _Pragma("unroll")                                                       \
        for (int t = 0; t < 4; t++) {                                           \
            int idx = tid + t * 256; int r = idx >> 3, c4 = (idx & 7) << 2;     \
            cpa16(ab + (r * 36 + c4) * 4, Ap + (m0 + r) * 1024 + kk + c4);      \
        }                                                                       \
        uint32_t bb = sB + (BUF) * 4352 * 4;                                    \
        _Pragma("unroll")                                                       \
        for (int t = 0; t < 4; t++) {                                           \
            int idx = tid + t * 256; int r = idx >> 5, c4 = (idx & 31) << 2;    \
            cpa16(bb + (r * 136 + c4) * 4, Bw + (size_t)(kk + r) * N + n0 + c4);\
        }                                                                       \
        cpcommit();                                                             \
    }

    STAGE(0, 0);
    for (int it = 0; it < 32; it++) {
        int buf = it & 1;
        if (it + 1 < 32) { STAGE(it + 1, buf ^ 1); cpwait<1>(); }
        else             { cpwait<0>(); }
        __syncthreads();
        const float* As_ = As + buf * 4608;
        const float* Bs_ = Bs + buf * 4352;
#pragma unroll
        for (int k8 = 0; k8 < 4; k8++) {
            uint32_t a[2][4];
#pragma unroll
            for (int mt = 0; mt < 2; mt++) {
                int r = wm * 32 + mt * 16 + (l >> 2);
                a[mt][0] = f2u(As_[r * 36 + k8 * 8 + (l & 3)]);
                a[mt][1] = f2u(As_[(r + 8) * 36 + k8 * 8 + (l & 3)]);
                a[mt][2] = f2u(As_[r * 36 + k8 * 8 + (l & 3) + 4]);
                a[mt][3] = f2u(As_[(r + 8) * 36 + k8 * 8 + (l & 3) + 4]);
            }
#pragma unroll
            for (int nt = 0; nt < 8; nt++) {
                uint32_t bf[2];
                int cb = wn * 64 + nt * 8 + (l >> 2);
                bf[0] = f2u(Bs_[(k8 * 8 + (l & 3)) * 136 + cb]);
                bf[1] = f2u(Bs_[(k8 * 8 + (l & 3) + 4) * 136 + cb]);
#pragma unroll
                for (int mt = 0; mt < 2; mt++)
                    mma8(acc[mt][nt], a[mt], bf, acc[mt][nt]);
            }
        }
        __syncthreads();
    }
#undef STAGE

    if (MODE == 0 && n0 >= 1024) {
        // K / V columns: write fp16 copies only (f32 never read)
        __half* dst = (n0 >= 2048) ? g_vh : g_kh;
        size_t cb = n0 - ((n0 >= 2048) ? 2048 : 1024);
#pragma unroll
        for (int mt = 0; mt < 2; mt++) {
            size_t r0 = m0 + wm * 32 + mt * 16 + (l >> 2);
#pragma unroll
            for (int nt = 0; nt < 8; nt++) {
                size_t c = cb + wn * 64 + nt * 8 + 2 * (l & 3);
                *(__half2*)(dst + r0 * 1024 + c) =
                    __floats2half2_rn(acc[mt][nt][0], acc[mt][nt][1]);
                *(__half2*)(dst + (r0 + 8) * 1024 + c) =
                    __floats2half2_rn(acc[mt][nt][2], acc[mt][nt][3]);
            }
        }
        return;
    }
#pragma unroll
    for (int mt = 0; mt < 2; mt++) {
        size_t r0 = m0 + wm * 32 + mt * 16 + (l >> 2);
#pragma unroll
        for (int nt = 0; nt < 8; nt++) {
            size_t c = n0 + wn * 64 + nt * 8 + 2 * (l & 3);
            float2 v0 = make_float2(acc[mt][nt][0], acc[mt][nt][1]);
            float2 v1 = make_float2(acc[mt][nt][2], acc[mt][nt][3]);
            if (MODE == 2) {
                float2 x0 = *(const float2*)(Xres + r0 * N + c);
                float2 x1 = *(const float2*)(Xres + (r0 + 8) * N + c);
                v0.x += x0.x; v0.y += x0.y; v1.x += x1.x; v1.y += x1.y;
            }
            *(float2*)(C + r0 * N + c) = v0;
            *(float2*)(C + (r0 + 8) * N + c) = v1;
        }
    }
}

// ============================================================
// Draw = (q + pos_bias_v) @ r^T per (b,h). 128x128, K=64, ldmatrix.
// Streaming stores (written once, read once later).
// ============================================================
__global__ __launch_bounds__(256, 2) void bd_gemm(const float* __restrict__ pbv)
{
    extern __shared__ float sm[];
    float* Qs = sm;               // 128 x 68
    float* Rs = sm + 8704;        // 128 x 68
    int tid = threadIdx.x, l = tid & 31, w = tid >> 5;
    int bh = blockIdx.z, b = bh >> 4, h = bh & 15;
    int i0 = blockIdx.y * 128, t0 = blockIdx.x * 128;
    const float* Qg = g_qkv + (size_t)b * QLD_ + h * 64;
    const float* Rg = g_r + h * 64;
    const float* bias = pbv + h * 64;

#pragma unroll
    for (int t = 0; t < 8; t++) {
        int idx = tid + t * 256; int r = idx >> 4, c4 = (idx & 15) << 2;
        float4 a4 = *(const float4*)(Qg + (size_t)(i0 + r) * ARS_ + c4);
        float4 u4 = *(const float4*)(bias + c4);
        a4.x += u4.x; a4.y += u4.y; a4.z += u4.z; a4.w += u4.w;
        *(float4*)&Qs[r * 68 + c4] = a4;
        *(float4*)&Rs[r * 68 + c4] = *(const float4*)(Rg + (size_t)(t0 + r) * D_ + c4);
    }
    __syncthreads();

    uint32_t sQ = (uint32_t)__cvta_generic_to_shared(Qs);
    uint32_t sR = (uint32_t)__cvta_generic_to_shared(Rs);
    uint32_t aoff = ((w * 16 + ((l >> 3) & 1) * 8 + (l & 7)) * 68 + ((l >> 4) & 1) * 4) * 4;
    uint32_t boff = ((((l >> 4) & 1) * 8 + (l & 7)) * 68 + ((l >> 3) & 1) * 4) * 4;

    uint32_t qa[8][4];
#pragma unroll
    for (int k8 = 0; k8 < 8; k8++) ldsm4(qa[k8], sQ + aoff + k8 * 32);

    float acc[16][4] = {};
#pragma unroll
    for (int k8 = 0; k8 < 8; k8++)
#pragma unroll
        for (int np = 0; np < 8; np++) {
            uint32_t kb[4];
            ldsm4(kb, sR + boff + np * 16 * 272 + k8 * 32);
            mma8(acc[2 * np],     qa[k8], kb,     acc[2 * np]);
            mma8(acc[2 * np + 1], qa[k8], kb + 2, acc[2 * np + 1]);
        }

    float* out = g_bd + (size_t)bh * S_ * S_;
    int gr = i0 + w * 16 + (l >> 2);
#pragma unroll
    for (int nt = 0; nt < 16; nt++) {
        int gc = t0 + nt * 8 + 2 * (l & 3);
        __stcs((float2*)(out + (size_t)gr * S_ + gc),
               make_float2(acc[nt][0], acc[nt][1]));
        __stcs((float2*)(out + (size_t)(gr + 8) * S_ + gc),
               make_float2(acc[nt][2], acc[nt][3]));
    }
}

// ============================================================
// Fused attention, all-fp16 mma paths:
//  AC: (q+u) fp16 x K fp16, m16n8k16 (Q smem fp16, K via ldsm4)
//  PV: P fp16 (reg cvt, no shuffles) x V fp16 (ldsm4t)
// BD gather pipelined in registers. smem 55 KB, 2 CTAs/SM.
// ============================================================
__device__ __forceinline__ float bdval(const float* bd, int i, int j)
{
    if (j <= i)      return __ldcs(bd + (size_t)i * S_ + (S_ - 1 + j - i));
    if (j == i + 1)  return 0.f;
    return __ldcs(bd + (size_t)(i + 1) * S_ + (j - i - 2));
}

__global__ __launch_bounds__(256, 2) void fattn(const float* __restrict__ pbu)
{
    extern __shared__ __half smh[];
    __half* Qsh = smh;                      // 128 x 72 fp16 (persistent)
    __half* Ksh = smh + 9216;               // 128 x 72 fp16
    __half* Vsh = smh + 18432;              // 128 x 72 fp16
    int tid = threadIdx.x, l = tid & 31, w = tid >> 5;
    int bh = blockIdx.y, b = bh >> 4, h = bh & 15;
    int i0 = blockIdx.x * 128;
    const float*  Qg = g_qkv + (size_t)b * QLD_ + h * 64;
    const __half* Kg = g_kh + (size_t)b * 1024 + h * 64;   // row stride 2048
    const __half* Vg = g_vh + (size_t)b * 1024 + h * 64;   // row stride 2048
    const float* bd = g_bd + (size_t)bh * S_ * S_;
    const float* bias = pbu + h * 64;
    uint32_t sQ = (uint32_t)__cvta_generic_to_shared(Qsh);
    uint32_t sK = (uint32_t)__cvta_generic_to_shared(Ksh);
    uint32_t sV = (uint32_t)__cvta_generic_to_shared(Vsh);

    // (q + bias_u) -> fp16 smem; prefetch K0 (group), V0 (group)
#pragma unroll
    for (int t = 0; t < 8; t++) {
        int idx = tid + t * 256; int r = idx >> 4, c4 = (idx & 15) << 2;
        float4 a4 = *(const float4*)(Qg + (size_t)(i0 + r) * ARS_ + c4);
        float4 u4 = *(const float4*)(bias + c4);
        *(__half2*)(Qsh + r * 72 + c4)     = __floats2half2_rn(a4.x + u4.x, a4.y + u4.y);
        *(__half2*)(Qsh + r * 72 + c4 + 2) = __floats2half2_rn(a4.z + u4.z, a4.w + u4.w);
    }
#pragma unroll
    for (int t = 0; t < 4; t++) {
        int idx = tid + t * 256; int r = idx >> 3, c8 = (idx & 7) << 3;
        cpa16(sK + (r * 72 + c8) * 2, Kg + (size_t)r * 2048 + c8);
    }
    cpcommit();
#pragma unroll
    for (int t = 0; t < 4; t++) {
        int idx = tid + t * 256; int r = idx >> 3, c8 = (idx & 7) << 3;
        cpa16(sV + (r * 72 + c8) * 2, Vg + (size_t)r * 2048 + c8);
    }
    cpcommit();

    // fp16 A-frag (Q rows w*16..w*16+15):
    uint32_t qoff  = (uint32_t)((w * 16 + (l & 7) + ((l >> 3) & 1) * 8) * 144
                                + ((l >> 4) & 1) * 16);
    // fp16 B-frag from row-major K (n = row, k-pairs contiguous):
    uint32_t kboff = (uint32_t)(((l & 7) + (l >> 4) * 8) * 144 + ((l >> 3) & 1) * 16);
    uint32_t vrbase = (uint32_t)((l & 7) + ((l >> 3) & 1) * 8);
    uint32_t vcoff  = (uint32_t)((l >> 4) * 8);

    float o[8][4] = {};
    float bdbuf[32];
    float mrow0 = -1e30f, mrow1 = -1e30f, lsum0 = 0.f, lsum1 = 0.f;
    int tc = l & 3;
    int lr0 = w * 16 + (l >> 2);
    int row0 = i0 + lr0, row1 = row0 + 8;
    const float CS = 0.1803368801111204f;   // 0.125 * log2(e)

#define LDBD(JB)                                                                \
    _Pragma("unroll")                                                           \
    for (int nt = 0; nt < 8; nt++) {                                            \
        int c0 = (JB) + nt * 8 + 2 * tc;                                        \
        bdbuf[nt * 4 + 0] = bdval(bd, row0, c0);                                \
        bdbuf[nt * 4 + 1] = bdval(bd, row0, c0 + 1);                            \
        bdbuf[nt * 4 + 2] = bdval(bd, row1, c0);                                \
        bdbuf[nt * 4 + 3] = bdval(bd, row1, c0 + 1);                            \
    }

    LDBD(0)              // BD for iter0/half0 — overlaps K0/V0 arrival
    __syncthreads();     // Qsh visible to ldmatrix

#define AC_MMA(HALF)                                                            \
    _Pragma("unroll")                                                           \
    for (int nt = 0; nt < 8; nt++)                                              \
        p[nt][0] = p[nt][1] = p[nt][2] = p[nt][3] = 0.f;                        \
    _Pragma("unroll")                                                           \
    for (int ks = 0; ks < 4; ks++) {                                            \
        uint32_t qf[4];                                                         \
        ldsm4(qf, sQ + qoff + ks * 32);                                         \
        _Pragma("unroll")                                                       \
        for (int np = 0; np < 4; np++) {                                        \
            uint32_t kb[4];                                                     \
            ldsm4(kb, sK + kboff + ((HALF) * 64 + np * 16) * 144 + ks * 32);    \
            mma16h(p[2 * np],     qf, kb,     p[2 * np]);                       \
            mma16h(p[2 * np + 1], qf, kb + 2, p[2 * np + 1]);                   \
        }                                                                       \
    }

#define SOFTMAX_STEP()                                                          \
    {                                                                           \
        float mx0 = -1e30f, mx1 = -1e30f;                                       \
        _Pragma("unroll")                                                       \
        for (int nt = 0; nt < 8; nt++) {                                        \
            float s;                                                            \
            s = (p[nt][0] + bdbuf[nt*4+0]) * CS; p[nt][0] = s; mx0 = fmaxf(mx0, s); \
            s = (p[nt][1] + bdbuf[nt*4+1]) * CS; p[nt][1] = s; mx0 = fmaxf(mx0, s); \
            s = (p[nt][2] + bdbuf[nt*4+2]) * CS; p[nt][2] = s; mx1 = fmaxf(mx1, s); \
            s = (p[nt][3] + bdbuf[nt*4+3]) * CS; p[nt][3] = s; mx1 = fmaxf(mx1, s); \
        }                                                                       \
        mx0 = fmaxf(mx0, __shfl_xor_sync(~0u, mx0, 1));                         \
        mx0 = fmaxf(mx0, __shfl_xor_sync(~0u, mx0, 2));                         \
        mx1 = fmaxf(mx1, __shfl_xor_sync(~0u, mx1, 1));                         \
        mx1 = fmaxf(mx1, __shfl_xor_sync(~0u, mx1, 2));                         \
        float mn0 = fmaxf(mrow0, mx0), mn1 = fmaxf(mrow1, mx1);                 \
        float al0 = ex2(mrow0 - mn0), al1 = ex2(mrow1 - mn1);                   \
        mrow0 = mn0; mrow1 = mn1;                                               \
        float rs0 = 0.f, rs1 = 0.f;                                             \
        _Pragma("unroll")                                                       \
        for (int nt = 0; nt < 8; nt++) {                                        \
            p[nt][0] = ex2(p[nt][0] - mn0); p[nt][1] = ex2(p[nt][1] - mn0);     \
            p[nt][2] = ex2(p[nt][2] - mn1); p[nt][3] = ex2(p[nt][3] - mn1);     \
            rs0 += p[nt][0] + p[nt][1]; rs1 += p[nt][2] + p[nt][3];             \
        }                                                                       \
        rs0 += __shfl_xor_sync(~0u, rs0, 1); rs0 += __shfl_xor_sync(~0u, rs0, 2);\
        rs1 += __shfl_xor_sync(~0u, rs1, 1); rs1 += __shfl_xor_sync(~0u, rs1, 2);\
        lsum0 = lsum0 * al0 + rs0;                                              \
        lsum1 = lsum1 * al1 + rs1;                                              \
        _Pragma("unroll")                                                       \
        for (int nt = 0; nt < 8; nt++) {                                        \
            o[nt][0] *= al0; o[nt][1] *= al0; o[nt][2] *= al1; o[nt][3] *= al1; \
        }                                                                       \
    }

#define CVT_P()                                                                 \
    uint32_t af[4][4];                                                          \
    _Pragma("unroll")                                                           \
    for (int ks = 0; ks < 4; ks++) {                                            \
        af[ks][0] = h2(p[2*ks][0],   p[2*ks][1]);                               \
        af[ks][1] = h2(p[2*ks][2],   p[2*ks][3]);                               \
        af[ks][2] = h2(p[2*ks+1][0], p[2*ks+1][1]);                             \
        af[ks][3] = h2(p[2*ks+1][2], p[2*ks+1][3]);                             \
    }

#define PV16(HALF)                                                              \
    _Pragma("unroll")                                                           \
    for (int ks = 0; ks < 4; ks++) {                                            \
        uint32_t vrow = (uint32_t)((HALF) * 64 + ks * 16) + vrbase;             \
        _Pragma("unroll")                                                       \
        for (int ntt = 0; ntt < 4; ntt++) {                                     \
            uint32_t vb[4];                                                     \
            ldsm4t(vb, sV + (vrow * 72 + ntt * 16 + vcoff) * 2);                \
            mma16h(o[2*ntt],   af[ks], vb,   o[2*ntt]);                         \
            mma16h(o[2*ntt+1], af[ks], vb+2, o[2*ntt+1]);                       \
        }                                                                       \
    }

    for (int it = 0; it < 16; it++) {
        cpwait<1>();          // K(it) landed; V(it) may be pending
        __syncthreads();      // all threads' K(it) visible

        {   // ---- half 0 ----
            float p[8][4];
            AC_MMA(0)
            SOFTMAX_STEP()
            CVT_P()           // p dead after this
            cpwait<0>();      // V(it) complete
            __syncthreads();
            LDBD(it * 128 + 64)   // BD half1 — covered by PV0 + AC1
            PV16(0)
        }
        {   // ---- half 1 ----
            float p[8][4];
            AC_MMA(1)
            SOFTMAX_STEP()
            CVT_P()
            __syncthreads();  // all warps done with Ksh
            if (it + 1 < 16) {
                const __half* kn = Kg + (size_t)((it + 1) * 128) * 2048;
#pragma unroll
                for (int t = 0; t < 4; t++) {
                    int idx = tid + t * 256; int r = idx >> 3, c8 = (idx & 7) << 3;
                    cpa16(sK + (r * 72 + c8) * 2, kn + (size_t)r * 2048 + c8);
                }
                cpcommit();
                LDBD((it + 1) * 128)   // BD next half0 — covered by PV1 + next AC0
            }
            PV16(1)
        }
        __syncthreads();      // all warps done reading Vsh
        if (it + 1 < 16) {
            const __half* vn = Vg + (size_t)((it + 1) * 128) * 2048;
#pragma unroll
            for (int t = 0; t < 4; t++) {
                int idx = tid + t * 256; int r = idx >> 3, c8 = (idx & 7) << 3;
                cpa16(sV + (r * 72 + c8) * 2, vn + (size_t)r * 2048 + c8);
            }
            cpcommit();
        }
    }
#undef LDBD
#undef AC_MMA
#undef SOFTMAX_STEP
#undef CVT_P
#undef PV16

    float inv0 = 1.f / lsum0, inv1 = 1.f / lsum1;
#pragma unroll
    for (int nt = 0; nt < 8; nt++) {
        int c = h * 64 + nt * 8 + 2 * tc;
        *(float2*)(g_att + ((size_t)row0 * B_ + b) * D_ + c) =
            make_float2(o[nt][0] * inv0, o[nt][1] * inv0);
        *(float2*)(g_att + ((size_t)row1 * B_ + b) * D_ + c) =
            make_float2(o[nt][2] * inv1, o[nt][3] * inv1);
    }
}

// ============================================================
// LayerNorm over D=1024 per row.
// ============================================================
__global__ __launch_bounds__(256) void ln_k(const float* __restrict__ gamma,
                                            const float* __restrict__ beta,
                                            float* __restrict__ out)
{
    __shared__ float reds[8], redq[8];
    const float* y = g_y + (size_t)blockIdx.x * D_;
    int tid = threadIdx.x;
    float v[4];
    float s = 0.f, q = 0.f;
#pragma unroll
    for (int t = 0; t < 4; t++) {
        v[t] = y[tid + t * 256];
        s += v[t]; q += v[t] * v[t];
    }
#pragma unroll
    for (int o = 16; o; o >>= 1) {
        s += __shfl_xor_sync(0xffffffffu, s, o);
        q += __shfl_xor_sync(0xffffffffu, q, o);
    }
    if ((tid & 31) == 0) { reds[tid >> 5] = s; redq[tid >> 5] = q; }
    __syncthreads();
    float ts = 0.f, tq = 0.f;
#pragma unroll
    for (int wv = 0; wv < 8; wv++) { ts += reds[wv]; tq += redq[wv]; }
    float mu = ts * (1.f / 1024.f);
    float var = tq * (1.f / 1024.f) - mu * mu;
    float inv = rsqrtf(var + 1e-5f);
    float* op = out + (size_t)blockIdx.x * D_;
#pragma unroll
    for (int t = 0; t < 4; t++) {
        int c = tid + t * 256;
        op[c] = (v[t] - mu) * inv * gamma[c] + beta[c];
    }
}

// ============================================================
extern "C" void kernel_launch(void* const* d_in, const int* in_sizes, int n_in,
                              void* d_out, int out_size)
{
    const float* x    = (const float*)d_in[0];
    const float* pe   = (const float*)d_in[1];
    const float* pbu  = (const float*)d_in[2];
    const float* pbv  = (const float*)d_in[3];
    const float* Wqkv = (const float*)d_in[4];
    const float* Wrel = (const float*)d_in[5];
    const float* Wo   = (const float*)d_in[6];
    const float* gam  = (const float*)d_in[7];
    const float* bet  = (const float*)d_in[8];
    float* out = (float*)d_out;

    const int PG_SMEM = 71680;     // (9216 + 8704) * 4
    const int BD_SMEM = 69632;     // 2 * 128*68 * 4
    const int FA_SMEM = 55296;     // 3 * 128*72 * 2
    cudaFuncSetAttribute(pgemm<0>, cudaFuncAttributeMaxDynamicSharedMemorySize, PG_SMEM);
    cudaFuncSetAttribute(pgemm<1>, cudaFuncAttributeMaxDynamicSharedMemorySize, PG_SMEM);
    cudaFuncSetAttribute(pgemm<2>, cudaFuncAttributeMaxDynamicSharedMemorySize, PG_SMEM);
    cudaFuncSetAttribute(bd_gemm,  cudaFuncAttributeMaxDynamicSharedMemorySize, BD_SMEM);
    cudaFuncSetAttribute(fattn,    cudaFuncAttributeMaxDynamicSharedMemorySize, FA_SMEM);

    // 1) qkv = x @ W_qkv  (q -> f32; k,v -> fp16)
    pgemm<0><<<dim3(24, 32), 256, PG_SMEM>>>(x, Wqkv, nullptr, 3072);
    // 2) r = pos_emb @ W_relemb
    pgemm<1><<<dim3(8, 16), 256, PG_SMEM>>>(pe, Wrel, nullptr, 1024);
    // 3) Draw = (q + pbv) @ r^T per (b,h)
    bd_gemm<<<dim3(16, 16, 32), 256, BD_SMEM>>>(pbv);
    // 4) fused: scores + rel-shift + softmax + PV
    fattn<<<dim3(16, 32), 256, FA_SMEM>>>(pbu);
    // 5) y = x + attn_vec @ W_o
    pgemm<2><<<dim3(8, 32), 256, PG_SMEM>>>(nullptr, Wo, x, 1024);
    // 6) layernorm
    ln_k<<<4096, 256>>>(gam, bet, out);
}